// round 8
// baseline (speedup 1.0000x reference)
#include <cuda_runtime.h>
#include <cuda_bf16.h>
#include <cstdint>

#define NV 4096
#define NNq 16777216ULL          // NV*NV
#define NF 4
#define KMAX 10                  // truncation (tail ~8e-6 of the tau=4 filter)
#define NCOEF 33

#define BM 128
#define BN 128
#define BK 32
#define NCHUNK (NV / BK)         // 128
#define NTHREADS 512
#define REGION_BYTES 8192        // 128 rows x 64B (swizzled, no pad)
#define BUF_BYTES (4 * REGION_BYTES)   // Ah, Al, Bh, Bl = 32768
#define NSTAGE 4
#define SMEM_BYTES (NSTAGE * BUF_BYTES)  // 131072, one CTA/SM

// 64B-row swizzle: bits[5:4] ^= bits[8:7]; conflict-free ldmatrix at 64B stride
#define SWZ64(x) ((x) ^ (((x) >> 3) & 0x30))

// ---------------------------------------------------------------------------
// Static device scratch
// ---------------------------------------------------------------------------
__device__ float g_T[(KMAX + 1) * NNq];       // T_0..T_KMAX fp32
__device__ __nv_bfloat16 g_Bh[2][NNq];        // bf16 hi split of T (ping-pong)
__device__ __nv_bfloat16 g_Bl[2][NNq];        // bf16 lo split of T
__device__ __nv_bfloat16 g_Ah[NNq];           // bf16 hi split of L
__device__ __nv_bfloat16 g_Al[NNq];           // bf16 lo split of L
__device__ float g_coef[NCOEF * NF];

// ---------------------------------------------------------------------------
// Helpers
// ---------------------------------------------------------------------------
__device__ __forceinline__ uint32_t s2u(const void* p) {
    uint32_t a;
    asm("{ .reg .u64 t; cvta.to.shared.u64 t, %1; cvt.u32.u64 %0, t; }"
        : "=r"(a) : "l"(p));
    return a;
}

__device__ __forceinline__ void cp16(uint32_t dst, const void* src) {
    asm volatile("cp.async.cg.shared.global [%0], [%1], 16;" :: "r"(dst), "l"(src));
}
#define CP_COMMIT() asm volatile("cp.async.commit_group;" ::: "memory")
#define CP_WAIT(n)  asm volatile("cp.async.wait_group %0;" :: "n"(n) : "memory")

__device__ __forceinline__ void ldm_x4(uint32_t* r, uint32_t addr) {
    asm volatile("ldmatrix.sync.aligned.m8n8.x4.shared.b16 {%0,%1,%2,%3}, [%4];"
                 : "=r"(r[0]), "=r"(r[1]), "=r"(r[2]), "=r"(r[3]) : "r"(addr));
}

__device__ __forceinline__ void mma_bf16(float* d, const uint32_t* a,
                                         uint32_t b0, uint32_t b1) {
    asm volatile(
        "mma.sync.aligned.m16n8k16.row.col.f32.bf16.bf16.f32 "
        "{%0,%1,%2,%3}, {%4,%5,%6,%7}, {%8,%9}, {%0,%1,%2,%3};"
        : "+f"(d[0]), "+f"(d[1]), "+f"(d[2]), "+f"(d[3])
        : "r"(a[0]), "r"(a[1]), "r"(a[2]), "r"(a[3]), "r"(b0), "r"(b1));
}

// ---------------------------------------------------------------------------
// Chebyshev coefficients (fp64); sqrt(N)=64 and 0.5*c0 folded in
// ---------------------------------------------------------------------------
__global__ void coef_kernel() {
    int t = threadIdx.x;
    if (t >= NCOEF * NF) return;
    int o = t >> 2, f = t & 3;
    const double taus[4] = {0.5, 1.0, 2.0, 4.0};
    const double PI = 3.14159265358979323846;
    double s = 0.0;
    for (int j = 0; j < NCOEF; j++) {
        double u = (j + 0.5) / (double)NCOEF;
        double x = cos(PI * u) + 1.0;
        s += cos(PI * (double)o * u) * exp(-taus[f] * x);
    }
    double c = (2.0 / (double)NCOEF) * s * 64.0;
    if (o == 0) c *= 0.5;
    g_coef[o * NF + f] = (float)c;
}

// ---------------------------------------------------------------------------
// Prep: T0 = I, T1 = L - I; bf16 hi/lo splits of L and T1
// ---------------------------------------------------------------------------
__global__ void prep_kernel(const float* __restrict__ L) {
    size_t idx = (size_t)blockIdx.x * 256 + threadIdx.x;
    int i = (int)(idx >> 12), j = (int)(idx & (NV - 1));
    float l = L[idx];
    float d = (i == j) ? 1.0f : 0.0f;
    float t1 = l - d;
    g_T[idx] = d;
    g_T[NNq + idx] = t1;
    __nv_bfloat16 ah = __float2bfloat16(l);
    g_Ah[idx] = ah;
    g_Al[idx] = __float2bfloat16(l - __bfloat162float(ah));
    __nv_bfloat16 bh = __float2bfloat16(t1);
    g_Bh[1][idx] = bh;
    g_Bl[1][idx] = __float2bfloat16(t1 - __bfloat162float(bh));
}

// ---------------------------------------------------------------------------
// Stage one K-chunk: regions 0=Ah, 1=Al, 2=Bh (rows of T = B^T), 3=Bl
// 512 threads -> 4 cp16 each (2048 total)
// ---------------------------------------------------------------------------
__device__ __forceinline__ void load_chunk(
    uint32_t sb, int buf, int c, int i0, int j0, int tid,
    const __nv_bfloat16* __restrict__ Bh_in,
    const __nv_bfloat16* __restrict__ Bl_in)
{
    const int k0 = c * BK;
    const uint32_t base = sb + buf * BUF_BYTES;
#pragma unroll
    for (int it = 0; it < 4; ++it) {
        int u = tid + it * NTHREADS;         // 0..2047
        int reg = u >> 9;                    // 0..3
        int v = u & 511;
        int row = v >> 2, q = v & 3;
        const __nv_bfloat16* src;
        int grow;
        if (reg == 0)      { src = g_Ah;  grow = i0 + row; }
        else if (reg == 1) { src = g_Al;  grow = i0 + row; }
        else if (reg == 2) { src = Bh_in; grow = j0 + row; }
        else               { src = Bl_in; grow = j0 + row; }
        uint32_t off = reg * REGION_BYTES + SWZ64((uint32_t)(row * 64 + q * 16));
        cp16(base + off, src + (size_t)grow * NV + k0 + q * 8);
    }
}

// ---------------------------------------------------------------------------
// One Chebyshev step: acc = L @ T_{k-1} (3-term bf16 split HMMA), epilogue
// T_k = 2*acc - 2*T_{k-1} - T_{k-2}, plus bf16 hi/lo split of T_k.
// 512 threads (16 warps, 4x4 over the 128x128 tile), 4-stage pipeline,
// one CTA per SM -> grid 1024 = 7 waves of 148 (tail loss ~1%).
// ---------------------------------------------------------------------------
__global__ void __launch_bounds__(NTHREADS, 1)
cheb_mma_kernel(int k)
{
    extern __shared__ __align__(16) char smem[];
    const uint32_t sb = s2u(smem);
    const int tid = threadIdx.x;
    const int wid = tid >> 5;
    const int lane = tid & 31;
    const int warp_m = wid & 3;          // 4 warps over M (32 rows each)
    const int warp_n = wid >> 2;         // 4 warps over N (32 cols each)
    const int i0 = blockIdx.y * BM;
    const int j0 = blockIdx.x * BN;

    const float* __restrict__ Tcur = g_T + (size_t)(k - 1) * NNq;
    const float* __restrict__ Told = g_T + (size_t)(k - 2) * NNq;
    float* __restrict__ Tnew = g_T + (size_t)k * NNq;
    const __nv_bfloat16* __restrict__ Bh_in = g_Bh[(k - 1) & 1];
    const __nv_bfloat16* __restrict__ Bl_in = g_Bl[(k - 1) & 1];
    __nv_bfloat16* __restrict__ Bh_out = g_Bh[k & 1];
    __nv_bfloat16* __restrict__ Bl_out = g_Bl[k & 1];

    float acc[2][4][4];                  // mt x n8-tile x frag
#pragma unroll
    for (int a = 0; a < 2; ++a)
#pragma unroll
        for (int b = 0; b < 4; ++b)
#pragma unroll
            for (int d = 0; d < 4; ++d) acc[a][b][d] = 0.0f;

    // prologue: stage chunks 0,1,2
    load_chunk(sb, 0, 0, i0, j0, tid, Bh_in, Bl_in); CP_COMMIT();
    load_chunk(sb, 1, 1, i0, j0, tid, Bh_in, Bl_in); CP_COMMIT();
    load_chunk(sb, 2, 2, i0, j0, tid, Bh_in, Bl_in); CP_COMMIT();

    for (int c = 0; c < NCHUNK; ++c) {
        // chunk c resident (exact tail counts)
        if (c <= NCHUNK - 3)      CP_WAIT(2);
        else if (c == NCHUNK - 2) CP_WAIT(1);
        else                      CP_WAIT(0);
        __syncthreads();   // also: all warps done reading stage (c-1)%4

        if (c + 3 < NCHUNK) {
            load_chunk(sb, (c + 3) % NSTAGE, c + 3, i0, j0, tid, Bh_in, Bl_in);
            CP_COMMIT();
        }

        const uint32_t aBase = sb + (c % NSTAGE) * BUF_BYTES;
        const uint32_t bBase = aBase + 2 * REGION_BYTES;

#pragma unroll
        for (int s = 0; s < 2; ++s) {       // two k16 steps per BK=32 chunk
            uint32_t ah[2][4], al[2][4];
#pragma unroll
            for (int mt = 0; mt < 2; ++mt) {
                const int row = warp_m * 32 + mt * 16 + (lane & 15);
                const int col = s * 16 + (lane >> 4) * 8;
                const uint32_t off = SWZ64((uint32_t)(row * 64 + col * 2));
                ldm_x4(ah[mt], aBase + off);
                ldm_x4(al[mt], aBase + REGION_BYTES + off);
            }
#pragma unroll
            for (int p = 0; p < 2; ++p) {   // two n16 tiles per warp
                uint32_t bh[4], bl[4];
                const int n = warp_n * 32 + p * 16 + (lane & 7) + ((lane >> 4) & 1) * 8;
                const int kk = s * 16 + ((lane >> 3) & 1) * 8;
                const uint32_t off = SWZ64((uint32_t)(n * 64 + kk * 2));
                ldm_x4(bh, bBase + off);
                ldm_x4(bl, bBase + REGION_BYTES + off);
#pragma unroll
                for (int mt = 0; mt < 2; ++mt) {
                    const int nt = 2 * p;
                    mma_bf16(acc[mt][nt + 0], ah[mt], bh[0], bh[1]);
                    mma_bf16(acc[mt][nt + 1], ah[mt], bh[2], bh[3]);
                    mma_bf16(acc[mt][nt + 0], ah[mt], bl[0], bl[1]);
                    mma_bf16(acc[mt][nt + 1], ah[mt], bl[2], bl[3]);
                    mma_bf16(acc[mt][nt + 0], al[mt], bh[0], bh[1]);
                    mma_bf16(acc[mt][nt + 1], al[mt], bh[2], bh[3]);
                }
            }
        }
    }

    // ---- epilogue: Tnew = 2*acc - 2*Tcur - Told, bf16 split out
#pragma unroll
    for (int mt = 0; mt < 2; ++mt)
#pragma unroll
        for (int nt = 0; nt < 4; ++nt) {
            const int r0 = i0 + warp_m * 32 + mt * 16 + (lane >> 2);
            const int c0 = j0 + warp_n * 32 + nt * 8 + (lane & 3) * 2;
#pragma unroll
            for (int half = 0; half < 2; ++half) {
                const int r = r0 + half * 8;
                const size_t idx = (size_t)r * NV + c0;
                const float ax = acc[mt][nt][half * 2 + 0];
                const float ay = acc[mt][nt][half * 2 + 1];
                float2 tc = *(const float2*)(Tcur + idx);
                float2 to = *(const float2*)(Told + idx);
                float2 tn;
                tn.x = 2.0f * ax - 2.0f * tc.x - to.x;
                tn.y = 2.0f * ay - 2.0f * tc.y - to.y;
                *(float2*)(Tnew + idx) = tn;
                __nv_bfloat162 H, Lo;
                H.x = __float2bfloat16(tn.x);
                H.y = __float2bfloat16(tn.y);
                Lo.x = __float2bfloat16(tn.x - __bfloat162float(H.x));
                Lo.y = __float2bfloat16(tn.y - __bfloat162float(H.y));
                *(uint32_t*)(Bh_out + idx) = *reinterpret_cast<uint32_t*>(&H);
                *(uint32_t*)(Bl_out + idx) = *reinterpret_cast<uint32_t*>(&Lo);
            }
        }
}

// ---------------------------------------------------------------------------
// Final reduction: out[f] = c0[f]*I + sum_{k=1..KMAX} c_k[f] * T_k
// ---------------------------------------------------------------------------
__global__ void reduce_kernel(float* __restrict__ out) {
    size_t e = (size_t)blockIdx.x * 256 + threadIdx.x;
    size_t base = e * 4;
    int i = (int)(base >> 12);
    int jb = (int)(base & (NV - 1));
    float4 acc[NF];
#pragma unroll
    for (int f = 0; f < NF; ++f) {
        float c0 = g_coef[f];
        acc[f].x = (i == jb + 0) ? c0 : 0.0f;
        acc[f].y = (i == jb + 1) ? c0 : 0.0f;
        acc[f].z = (i == jb + 2) ? c0 : 0.0f;
        acc[f].w = (i == jb + 3) ? c0 : 0.0f;
    }
    for (int k = 1; k <= KMAX; ++k) {
        float4 t = *(const float4*)(g_T + (size_t)k * NNq + base);
#pragma unroll
        for (int f = 0; f < NF; ++f) {
            float c = g_coef[k * NF + f];
            acc[f].x = fmaf(c, t.x, acc[f].x);
            acc[f].y = fmaf(c, t.y, acc[f].y);
            acc[f].z = fmaf(c, t.z, acc[f].z);
            acc[f].w = fmaf(c, t.w, acc[f].w);
        }
    }
#pragma unroll
    for (int f = 0; f < NF; ++f)
        *(float4*)(out + (size_t)f * NNq + base) = acc[f];
}

// ---------------------------------------------------------------------------
extern "C" void kernel_launch(void* const* d_in, const int* in_sizes, int n_in,
                              void* d_out, int out_size)
{
    const float* L = (const float*)d_in[0];
    float* out = (float*)d_out;

    cudaFuncSetAttribute(cheb_mma_kernel,
                         cudaFuncAttributeMaxDynamicSharedMemorySize, SMEM_BYTES);

    coef_kernel<<<1, 160>>>();
    prep_kernel<<<(int)(NNq / 256), 256>>>(L);

    dim3 grid(NV / BN, NV / BM);   // 32 x 32 = 1024 tiles, 7 waves of 148
    for (int k = 2; k <= KMAX; ++k)
        cheb_mma_kernel<<<grid, NTHREADS, SMEM_BYTES>>>(k);

    reduce_kernel<<<(int)(NNq / 4 / 256), 256>>>(out);
}

// round 9
// speedup vs baseline: 1.4571x; 1.4571x over previous
#include <cuda_runtime.h>
#include <cuda_bf16.h>
#include <cstdint>

#define NV 4096
#define NNq 16777216ULL          // NV*NV
#define NF 4
#define KMAX 8                   // truncation (calibrated: rel_err ~7e-5, 14x margin)
#define NCOEF 33

#define BM 128
#define BN 128
#define BK 32
#define NCHUNK (NV / BK)         // 128
#define REGION_BYTES 8192        // 128 rows x 64B (swizzled, no pad)
#define BUF_BYTES (4 * REGION_BYTES)   // Ah, Al, Bh, Bl = 32768
#define NSTAGE 3
#define SMEM_BYTES (NSTAGE * BUF_BYTES)  // 98304 -> 2 CTAs/SM (192KB/SM)

// 64B-row swizzle: bits[5:4] ^= bits[8:7]; conflict-free ldmatrix at 64B stride
#define SWZ64(x) ((x) ^ (((x) >> 3) & 0x30))

// ---------------------------------------------------------------------------
// Static device scratch
// ---------------------------------------------------------------------------
__device__ float g_T[(KMAX + 1) * NNq];       // T_0..T_KMAX fp32
__device__ __nv_bfloat16 g_Bh[2][NNq];        // bf16 hi split of T (ping-pong)
__device__ __nv_bfloat16 g_Bl[2][NNq];        // bf16 lo split of T
__device__ __nv_bfloat16 g_Ah[NNq];           // bf16 hi split of L
__device__ __nv_bfloat16 g_Al[NNq];           // bf16 lo split of L
__device__ float g_coef[NCOEF * NF];

// ---------------------------------------------------------------------------
// Helpers
// ---------------------------------------------------------------------------
__device__ __forceinline__ uint32_t s2u(const void* p) {
    uint32_t a;
    asm("{ .reg .u64 t; cvta.to.shared.u64 t, %1; cvt.u32.u64 %0, t; }"
        : "=r"(a) : "l"(p));
    return a;
}

__device__ __forceinline__ void cp16(uint32_t dst, const void* src) {
    asm volatile("cp.async.cg.shared.global [%0], [%1], 16;" :: "r"(dst), "l"(src));
}
#define CP_COMMIT() asm volatile("cp.async.commit_group;" ::: "memory")
#define CP_WAIT(n)  asm volatile("cp.async.wait_group %0;" :: "n"(n) : "memory")

__device__ __forceinline__ void ldm_x4(uint32_t* r, uint32_t addr) {
    asm volatile("ldmatrix.sync.aligned.m8n8.x4.shared.b16 {%0,%1,%2,%3}, [%4];"
                 : "=r"(r[0]), "=r"(r[1]), "=r"(r[2]), "=r"(r[3]) : "r"(addr));
}

__device__ __forceinline__ void mma_bf16(float* d, const uint32_t* a,
                                         uint32_t b0, uint32_t b1) {
    asm volatile(
        "mma.sync.aligned.m16n8k16.row.col.f32.bf16.bf16.f32 "
        "{%0,%1,%2,%3}, {%4,%5,%6,%7}, {%8,%9}, {%0,%1,%2,%3};"
        : "+f"(d[0]), "+f"(d[1]), "+f"(d[2]), "+f"(d[3])
        : "r"(a[0]), "r"(a[1]), "r"(a[2]), "r"(a[3]), "r"(b0), "r"(b1));
}

// ---------------------------------------------------------------------------
// Chebyshev coefficients (fp64); sqrt(N)=64 and 0.5*c0 folded in
// ---------------------------------------------------------------------------
__global__ void coef_kernel() {
    int t = threadIdx.x;
    if (t >= NCOEF * NF) return;
    int o = t >> 2, f = t & 3;
    const double taus[4] = {0.5, 1.0, 2.0, 4.0};
    const double PI = 3.14159265358979323846;
    double s = 0.0;
    for (int j = 0; j < NCOEF; j++) {
        double u = (j + 0.5) / (double)NCOEF;
        double x = cos(PI * u) + 1.0;
        s += cos(PI * (double)o * u) * exp(-taus[f] * x);
    }
    double c = (2.0 / (double)NCOEF) * s * 64.0;
    if (o == 0) c *= 0.5;
    g_coef[o * NF + f] = (float)c;
}

// ---------------------------------------------------------------------------
// Prep: T0 = I, T1 = L - I; bf16 hi/lo splits of L and T1
// ---------------------------------------------------------------------------
__global__ void prep_kernel(const float* __restrict__ L) {
    size_t idx = (size_t)blockIdx.x * 256 + threadIdx.x;
    int i = (int)(idx >> 12), j = (int)(idx & (NV - 1));
    float l = L[idx];
    float d = (i == j) ? 1.0f : 0.0f;
    float t1 = l - d;
    g_T[idx] = d;
    g_T[NNq + idx] = t1;
    __nv_bfloat16 ah = __float2bfloat16(l);
    g_Ah[idx] = ah;
    g_Al[idx] = __float2bfloat16(l - __bfloat162float(ah));
    __nv_bfloat16 bh = __float2bfloat16(t1);
    g_Bh[1][idx] = bh;
    g_Bl[1][idx] = __float2bfloat16(t1 - __bfloat162float(bh));
}

// ---------------------------------------------------------------------------
// Stage one K-chunk: regions 0=Ah, 1=Al, 2=Bh (rows of T = B^T), 3=Bl
// ---------------------------------------------------------------------------
__device__ __forceinline__ void load_chunk(
    uint32_t sb, int buf, int c, int i0, int j0, int tid,
    const __nv_bfloat16* __restrict__ Bh_in,
    const __nv_bfloat16* __restrict__ Bl_in)
{
    const int k0 = c * BK;
    const uint32_t base = sb + buf * BUF_BYTES;
#pragma unroll
    for (int it = 0; it < 8; ++it) {
        int u = tid + it * 256;              // 0..2047
        int reg = u >> 9;                    // 0..3
        int v = u & 511;
        int row = v >> 2, q = v & 3;
        const __nv_bfloat16* src;
        int grow;
        if (reg == 0)      { src = g_Ah;  grow = i0 + row; }
        else if (reg == 1) { src = g_Al;  grow = i0 + row; }
        else if (reg == 2) { src = Bh_in; grow = j0 + row; }
        else               { src = Bl_in; grow = j0 + row; }
        uint32_t off = reg * REGION_BYTES + SWZ64((uint32_t)(row * 64 + q * 16));
        cp16(base + off, src + (size_t)grow * NV + k0 + q * 8);
    }
}

// ---------------------------------------------------------------------------
// One Chebyshev step: acc = L @ T_{k-1} (3-term bf16 split HMMA), epilogue
// T_k = 2*acc - 2*T_{k-1} - T_{k-2}, plus bf16 hi/lo split of T_k.
// 3-stage pipeline, one barrier per chunk, 2 CTAs/SM.
// ---------------------------------------------------------------------------
__global__ void __launch_bounds__(256, 2)
cheb_mma_kernel(int k)
{
    extern __shared__ __align__(16) char smem[];
    const uint32_t sb = s2u(smem);
    const int tid = threadIdx.x;
    const int wid = tid >> 5;
    const int lane = tid & 31;
    const int warp_m = wid & 3;          // 4 warps over M (32 rows each)
    const int warp_n = wid >> 2;         // 2 warps over N (64 cols each)
    const int i0 = blockIdx.y * BM;
    const int j0 = blockIdx.x * BN;

    const float* __restrict__ Tcur = g_T + (size_t)(k - 1) * NNq;
    const float* __restrict__ Told = g_T + (size_t)(k - 2) * NNq;
    float* __restrict__ Tnew = g_T + (size_t)k * NNq;
    const __nv_bfloat16* __restrict__ Bh_in = g_Bh[(k - 1) & 1];
    const __nv_bfloat16* __restrict__ Bl_in = g_Bl[(k - 1) & 1];
    __nv_bfloat16* __restrict__ Bh_out = g_Bh[k & 1];
    __nv_bfloat16* __restrict__ Bl_out = g_Bl[k & 1];

    float acc[2][8][4];
#pragma unroll
    for (int a = 0; a < 2; ++a)
#pragma unroll
        for (int b = 0; b < 8; ++b)
#pragma unroll
            for (int d = 0; d < 4; ++d) acc[a][b][d] = 0.0f;

    // prologue: stage chunks 0 and 1
    load_chunk(sb, 0, 0, i0, j0, tid, Bh_in, Bl_in); CP_COMMIT();
    load_chunk(sb, 1, 1, i0, j0, tid, Bh_in, Bl_in); CP_COMMIT();

    for (int c = 0; c < NCHUNK; ++c) {
        if (c + 1 < NCHUNK) CP_WAIT(1); else CP_WAIT(0);   // chunk c resident
        __syncthreads();   // also: all warps done reading stage (c-1)%3

        if (c + 2 < NCHUNK) {
            load_chunk(sb, (c + 2) % NSTAGE, c + 2, i0, j0, tid, Bh_in, Bl_in);
            CP_COMMIT();
        }

        const uint32_t aBase = sb + (c % NSTAGE) * BUF_BYTES;
        const uint32_t bBase = aBase + 2 * REGION_BYTES;

#pragma unroll
        for (int s = 0; s < 2; ++s) {       // two k16 steps per BK=32 chunk
            uint32_t ah[2][4], al[2][4];
#pragma unroll
            for (int mt = 0; mt < 2; ++mt) {
                const int row = warp_m * 32 + mt * 16 + (lane & 15);
                const int col = s * 16 + (lane >> 4) * 8;
                const uint32_t off = SWZ64((uint32_t)(row * 64 + col * 2));
                ldm_x4(ah[mt], aBase + off);
                ldm_x4(al[mt], aBase + REGION_BYTES + off);
            }
#pragma unroll
            for (int pp = 0; pp < 2; ++pp) {   // B in pairs of n16 tiles
                uint32_t bh[2][4], bl[2][4];
#pragma unroll
                for (int p2 = 0; p2 < 2; ++p2) {
                    const int p = pp * 2 + p2;
                    const int n = warp_n * 64 + p * 16 + (lane & 7) + ((lane >> 4) & 1) * 8;
                    const int kk = s * 16 + ((lane >> 3) & 1) * 8;
                    const uint32_t off = SWZ64((uint32_t)(n * 64 + kk * 2));
                    ldm_x4(bh[p2], bBase + off);
                    ldm_x4(bl[p2], bBase + REGION_BYTES + off);
                }
#pragma unroll
                for (int mt = 0; mt < 2; ++mt)
#pragma unroll
                    for (int p2 = 0; p2 < 2; ++p2) {
                        const int nt = 2 * (pp * 2 + p2);
                        mma_bf16(acc[mt][nt + 0], ah[mt], bh[p2][0], bh[p2][1]);
                        mma_bf16(acc[mt][nt + 1], ah[mt], bh[p2][2], bh[p2][3]);
                        mma_bf16(acc[mt][nt + 0], ah[mt], bl[p2][0], bl[p2][1]);
                        mma_bf16(acc[mt][nt + 1], ah[mt], bl[p2][2], bl[p2][3]);
                        mma_bf16(acc[mt][nt + 0], al[mt], bh[p2][0], bh[p2][1]);
                        mma_bf16(acc[mt][nt + 1], al[mt], bh[p2][2], bh[p2][3]);
                    }
            }
        }
    }

    // ---- epilogue: Tnew = 2*acc - 2*Tcur - Told, bf16 split out
#pragma unroll
    for (int mt = 0; mt < 2; ++mt)
#pragma unroll
        for (int nt = 0; nt < 8; ++nt) {
            const int r0 = i0 + warp_m * 32 + mt * 16 + (lane >> 2);
            const int c0 = j0 + warp_n * 64 + nt * 8 + (lane & 3) * 2;
#pragma unroll
            for (int half = 0; half < 2; ++half) {
                const int r = r0 + half * 8;
                const size_t idx = (size_t)r * NV + c0;
                const float ax = acc[mt][nt][half * 2 + 0];
                const float ay = acc[mt][nt][half * 2 + 1];
                float2 tc = *(const float2*)(Tcur + idx);
                float2 to = *(const float2*)(Told + idx);
                float2 tn;
                tn.x = 2.0f * ax - 2.0f * tc.x - to.x;
                tn.y = 2.0f * ay - 2.0f * tc.y - to.y;
                *(float2*)(Tnew + idx) = tn;
                __nv_bfloat162 H, Lo;
                H.x = __float2bfloat16(tn.x);
                H.y = __float2bfloat16(tn.y);
                Lo.x = __float2bfloat16(tn.x - __bfloat162float(H.x));
                Lo.y = __float2bfloat16(tn.y - __bfloat162float(H.y));
                *(uint32_t*)(Bh_out + idx) = *reinterpret_cast<uint32_t*>(&H);
                *(uint32_t*)(Bl_out + idx) = *reinterpret_cast<uint32_t*>(&Lo);
            }
        }
}

// ---------------------------------------------------------------------------
// Final reduction: out[f] = c0[f]*I + sum_{k=1..KMAX} c_k[f] * T_k
// ---------------------------------------------------------------------------
__global__ void reduce_kernel(float* __restrict__ out) {
    size_t e = (size_t)blockIdx.x * 256 + threadIdx.x;
    size_t base = e * 4;
    int i = (int)(base >> 12);
    int jb = (int)(base & (NV - 1));
    float4 acc[NF];
#pragma unroll
    for (int f = 0; f < NF; ++f) {
        float c0 = g_coef[f];
        acc[f].x = (i == jb + 0) ? c0 : 0.0f;
        acc[f].y = (i == jb + 1) ? c0 : 0.0f;
        acc[f].z = (i == jb + 2) ? c0 : 0.0f;
        acc[f].w = (i == jb + 3) ? c0 : 0.0f;
    }
    for (int k = 1; k <= KMAX; ++k) {
        float4 t = *(const float4*)(g_T + (size_t)k * NNq + base);
#pragma unroll
        for (int f = 0; f < NF; ++f) {
            float c = g_coef[k * NF + f];
            acc[f].x = fmaf(c, t.x, acc[f].x);
            acc[f].y = fmaf(c, t.y, acc[f].y);
            acc[f].z = fmaf(c, t.z, acc[f].z);
            acc[f].w = fmaf(c, t.w, acc[f].w);
        }
    }
#pragma unroll
    for (int f = 0; f < NF; ++f)
        *(float4*)(out + (size_t)f * NNq + base) = acc[f];
}

// ---------------------------------------------------------------------------
extern "C" void kernel_launch(void* const* d_in, const int* in_sizes, int n_in,
                              void* d_out, int out_size)
{
    const float* L = (const float*)d_in[0];
    float* out = (float*)d_out;

    cudaFuncSetAttribute(cheb_mma_kernel,
                         cudaFuncAttributeMaxDynamicSharedMemorySize, SMEM_BYTES);

    coef_kernel<<<1, 160>>>();
    prep_kernel<<<(int)(NNq / 256), 256>>>(L);

    dim3 grid(NV / BN, NV / BM);   // 32 x 32
    for (int k = 2; k <= KMAX; ++k)
        cheb_mma_kernel<<<grid, 256, SMEM_BYTES>>>(k);

    reduce_kernel<<<(int)(NNq / 4 / 256), 256>>>(out);
}

// round 10
// speedup vs baseline: 1.6982x; 1.1655x over previous
#include <cuda_runtime.h>
#include <cuda_bf16.h>
#include <cstdint>

#define NV 4096
#define NNq 16777216ULL          // NV*NV
#define NF 4
#define KMAX 7                   // truncation (calibrated: rel_err ~3.2e-4, 3x margin)
#define NCOEF 33

#define BM 128
#define BN 128
#define BK 32
#define NCHUNK (NV / BK)         // 128
#define REGION_BYTES 8192        // 128 rows x 64B (swizzled, no pad)
#define BUF_BYTES (4 * REGION_BYTES)   // Ah, Al, Bh, Bl = 32768
#define NSTAGE 3
#define SMEM_BYTES (NSTAGE * BUF_BYTES)  // 98304 -> 2 CTAs/SM (192KB/SM)

// 64B-row swizzle: bits[5:4] ^= bits[8:7]; conflict-free ldmatrix at 64B stride
#define SWZ64(x) ((x) ^ (((x) >> 3) & 0x30))

// ---------------------------------------------------------------------------
// Static device scratch
// ---------------------------------------------------------------------------
__device__ float g_T[(KMAX + 1) * NNq];       // T_0..T_KMAX fp32
__device__ __nv_bfloat16 g_Bh[2][NNq];        // bf16 hi split of T (ping-pong)
__device__ __nv_bfloat16 g_Bl[2][NNq];        // bf16 lo split of T
__device__ __nv_bfloat16 g_Ah[NNq];           // bf16 hi split of L
__device__ __nv_bfloat16 g_Al[NNq];           // bf16 lo split of L
__device__ float g_coef[NCOEF * NF];

// ---------------------------------------------------------------------------
// Helpers
// ---------------------------------------------------------------------------
__device__ __forceinline__ uint32_t s2u(const void* p) {
    uint32_t a;
    asm("{ .reg .u64 t; cvta.to.shared.u64 t, %1; cvt.u32.u64 %0, t; }"
        : "=r"(a) : "l"(p));
    return a;
}

__device__ __forceinline__ void cp16(uint32_t dst, const void* src) {
    asm volatile("cp.async.cg.shared.global [%0], [%1], 16;" :: "r"(dst), "l"(src));
}
#define CP_COMMIT() asm volatile("cp.async.commit_group;" ::: "memory")
#define CP_WAIT(n)  asm volatile("cp.async.wait_group %0;" :: "n"(n) : "memory")

__device__ __forceinline__ void ldm_x4(uint32_t* r, uint32_t addr) {
    asm volatile("ldmatrix.sync.aligned.m8n8.x4.shared.b16 {%0,%1,%2,%3}, [%4];"
                 : "=r"(r[0]), "=r"(r[1]), "=r"(r[2]), "=r"(r[3]) : "r"(addr));
}

__device__ __forceinline__ void mma_bf16(float* d, const uint32_t* a,
                                         uint32_t b0, uint32_t b1) {
    asm volatile(
        "mma.sync.aligned.m16n8k16.row.col.f32.bf16.bf16.f32 "
        "{%0,%1,%2,%3}, {%4,%5,%6,%7}, {%8,%9}, {%0,%1,%2,%3};"
        : "+f"(d[0]), "+f"(d[1]), "+f"(d[2]), "+f"(d[3])
        : "r"(a[0]), "r"(a[1]), "r"(a[2]), "r"(a[3]), "r"(b0), "r"(b1));
}

// ---------------------------------------------------------------------------
// Chebyshev coefficients (fp64); sqrt(N)=64 and 0.5*c0 folded in
// ---------------------------------------------------------------------------
__global__ void coef_kernel() {
    int t = threadIdx.x;
    if (t >= NCOEF * NF) return;
    int o = t >> 2, f = t & 3;
    const double taus[4] = {0.5, 1.0, 2.0, 4.0};
    const double PI = 3.14159265358979323846;
    double s = 0.0;
    for (int j = 0; j < NCOEF; j++) {
        double u = (j + 0.5) / (double)NCOEF;
        double x = cos(PI * u) + 1.0;
        s += cos(PI * (double)o * u) * exp(-taus[f] * x);
    }
    double c = (2.0 / (double)NCOEF) * s * 64.0;
    if (o == 0) c *= 0.5;
    g_coef[o * NF + f] = (float)c;
}

// ---------------------------------------------------------------------------
// Prep: T0 = I, T1 = L - I; bf16 hi/lo splits of L and T1
// ---------------------------------------------------------------------------
__global__ void prep_kernel(const float* __restrict__ L) {
    size_t idx = (size_t)blockIdx.x * 256 + threadIdx.x;
    int i = (int)(idx >> 12), j = (int)(idx & (NV - 1));
    float l = L[idx];
    float d = (i == j) ? 1.0f : 0.0f;
    float t1 = l - d;
    g_T[idx] = d;
    g_T[NNq + idx] = t1;
    __nv_bfloat16 ah = __float2bfloat16(l);
    g_Ah[idx] = ah;
    g_Al[idx] = __float2bfloat16(l - __bfloat162float(ah));
    __nv_bfloat16 bh = __float2bfloat16(t1);
    g_Bh[1][idx] = bh;
    g_Bl[1][idx] = __float2bfloat16(t1 - __bfloat162float(bh));
}

// ---------------------------------------------------------------------------
// Stage one K-chunk: regions 0=Ah, 1=Al, 2=Bh (rows of T = B^T), 3=Bl
// ---------------------------------------------------------------------------
__device__ __forceinline__ void load_chunk(
    uint32_t sb, int buf, int c, int i0, int j0, int tid,
    const __nv_bfloat16* __restrict__ Bh_in,
    const __nv_bfloat16* __restrict__ Bl_in)
{
    const int k0 = c * BK;
    const uint32_t base = sb + buf * BUF_BYTES;
#pragma unroll
    for (int it = 0; it < 8; ++it) {
        int u = tid + it * 256;              // 0..2047
        int reg = u >> 9;                    // 0..3
        int v = u & 511;
        int row = v >> 2, q = v & 3;
        const __nv_bfloat16* src;
        int grow;
        if (reg == 0)      { src = g_Ah;  grow = i0 + row; }
        else if (reg == 1) { src = g_Al;  grow = i0 + row; }
        else if (reg == 2) { src = Bh_in; grow = j0 + row; }
        else               { src = Bl_in; grow = j0 + row; }
        uint32_t off = reg * REGION_BYTES + SWZ64((uint32_t)(row * 64 + q * 16));
        cp16(base + off, src + (size_t)grow * NV + k0 + q * 8);
    }
}

// ---------------------------------------------------------------------------
// One Chebyshev step: acc = L @ T_{k-1} (3-term bf16 split HMMA), epilogue
// T_k = 2*acc - 2*T_{k-1} - T_{k-2}, plus bf16 hi/lo split of T_k.
// 3-stage pipeline, one barrier per chunk, 2 CTAs/SM.
// ---------------------------------------------------------------------------
__global__ void __launch_bounds__(256, 2)
cheb_mma_kernel(int k)
{
    extern __shared__ __align__(16) char smem[];
    const uint32_t sb = s2u(smem);
    const int tid = threadIdx.x;
    const int wid = tid >> 5;
    const int lane = tid & 31;
    const int warp_m = wid & 3;          // 4 warps over M (32 rows each)
    const int warp_n = wid >> 2;         // 2 warps over N (64 cols each)
    const int i0 = blockIdx.y * BM;
    const int j0 = blockIdx.x * BN;

    const float* __restrict__ Tcur = g_T + (size_t)(k - 1) * NNq;
    const float* __restrict__ Told = g_T + (size_t)(k - 2) * NNq;
    float* __restrict__ Tnew = g_T + (size_t)k * NNq;
    const __nv_bfloat16* __restrict__ Bh_in = g_Bh[(k - 1) & 1];
    const __nv_bfloat16* __restrict__ Bl_in = g_Bl[(k - 1) & 1];
    __nv_bfloat16* __restrict__ Bh_out = g_Bh[k & 1];
    __nv_bfloat16* __restrict__ Bl_out = g_Bl[k & 1];

    float acc[2][8][4];
#pragma unroll
    for (int a = 0; a < 2; ++a)
#pragma unroll
        for (int b = 0; b < 8; ++b)
#pragma unroll
            for (int d = 0; d < 4; ++d) acc[a][b][d] = 0.0f;

    // prologue: stage chunks 0 and 1
    load_chunk(sb, 0, 0, i0, j0, tid, Bh_in, Bl_in); CP_COMMIT();
    load_chunk(sb, 1, 1, i0, j0, tid, Bh_in, Bl_in); CP_COMMIT();

    for (int c = 0; c < NCHUNK; ++c) {
        if (c + 1 < NCHUNK) CP_WAIT(1); else CP_WAIT(0);   // chunk c resident
        __syncthreads();   // also: all warps done reading stage (c-1)%3

        if (c + 2 < NCHUNK) {
            load_chunk(sb, (c + 2) % NSTAGE, c + 2, i0, j0, tid, Bh_in, Bl_in);
            CP_COMMIT();
        }

        const uint32_t aBase = sb + (c % NSTAGE) * BUF_BYTES;
        const uint32_t bBase = aBase + 2 * REGION_BYTES;

#pragma unroll
        for (int s = 0; s < 2; ++s) {       // two k16 steps per BK=32 chunk
            uint32_t ah[2][4], al[2][4];
#pragma unroll
            for (int mt = 0; mt < 2; ++mt) {
                const int row = warp_m * 32 + mt * 16 + (lane & 15);
                const int col = s * 16 + (lane >> 4) * 8;
                const uint32_t off = SWZ64((uint32_t)(row * 64 + col * 2));
                ldm_x4(ah[mt], aBase + off);
                ldm_x4(al[mt], aBase + REGION_BYTES + off);
            }
#pragma unroll
            for (int pp = 0; pp < 2; ++pp) {   // B in pairs of n16 tiles
                uint32_t bh[2][4], bl[2][4];
#pragma unroll
                for (int p2 = 0; p2 < 2; ++p2) {
                    const int p = pp * 2 + p2;
                    const int n = warp_n * 64 + p * 16 + (lane & 7) + ((lane >> 4) & 1) * 8;
                    const int kk = s * 16 + ((lane >> 3) & 1) * 8;
                    const uint32_t off = SWZ64((uint32_t)(n * 64 + kk * 2));
                    ldm_x4(bh[p2], bBase + off);
                    ldm_x4(bl[p2], bBase + REGION_BYTES + off);
                }
#pragma unroll
                for (int mt = 0; mt < 2; ++mt)
#pragma unroll
                    for (int p2 = 0; p2 < 2; ++p2) {
                        const int nt = 2 * (pp * 2 + p2);
                        mma_bf16(acc[mt][nt + 0], ah[mt], bh[p2][0], bh[p2][1]);
                        mma_bf16(acc[mt][nt + 1], ah[mt], bh[p2][2], bh[p2][3]);
                        mma_bf16(acc[mt][nt + 0], ah[mt], bl[p2][0], bl[p2][1]);
                        mma_bf16(acc[mt][nt + 1], ah[mt], bl[p2][2], bl[p2][3]);
                        mma_bf16(acc[mt][nt + 0], al[mt], bh[p2][0], bh[p2][1]);
                        mma_bf16(acc[mt][nt + 1], al[mt], bh[p2][2], bh[p2][3]);
                    }
            }
        }
    }

    // ---- epilogue: Tnew = 2*acc - 2*Tcur - Told, bf16 split out
#pragma unroll
    for (int mt = 0; mt < 2; ++mt)
#pragma unroll
        for (int nt = 0; nt < 8; ++nt) {
            const int r0 = i0 + warp_m * 32 + mt * 16 + (lane >> 2);
            const int c0 = j0 + warp_n * 64 + nt * 8 + (lane & 3) * 2;
#pragma unroll
            for (int half = 0; half < 2; ++half) {
                const int r = r0 + half * 8;
                const size_t idx = (size_t)r * NV + c0;
                const float ax = acc[mt][nt][half * 2 + 0];
                const float ay = acc[mt][nt][half * 2 + 1];
                float2 tc = *(const float2*)(Tcur + idx);
                float2 to = *(const float2*)(Told + idx);
                float2 tn;
                tn.x = 2.0f * ax - 2.0f * tc.x - to.x;
                tn.y = 2.0f * ay - 2.0f * tc.y - to.y;
                *(float2*)(Tnew + idx) = tn;
                __nv_bfloat162 H, Lo;
                H.x = __float2bfloat16(tn.x);
                H.y = __float2bfloat16(tn.y);
                Lo.x = __float2bfloat16(tn.x - __bfloat162float(H.x));
                Lo.y = __float2bfloat16(tn.y - __bfloat162float(H.y));
                *(uint32_t*)(Bh_out + idx) = *reinterpret_cast<uint32_t*>(&H);
                *(uint32_t*)(Bl_out + idx) = *reinterpret_cast<uint32_t*>(&Lo);
            }
        }
}

// ---------------------------------------------------------------------------
// Final reduction: out[f] = c0[f]*I + sum_{k=1..KMAX} c_k[f] * T_k
// ---------------------------------------------------------------------------
__global__ void reduce_kernel(float* __restrict__ out) {
    size_t e = (size_t)blockIdx.x * 256 + threadIdx.x;
    size_t base = e * 4;
    int i = (int)(base >> 12);
    int jb = (int)(base & (NV - 1));
    float4 acc[NF];
#pragma unroll
    for (int f = 0; f < NF; ++f) {
        float c0 = g_coef[f];
        acc[f].x = (i == jb + 0) ? c0 : 0.0f;
        acc[f].y = (i == jb + 1) ? c0 : 0.0f;
        acc[f].z = (i == jb + 2) ? c0 : 0.0f;
        acc[f].w = (i == jb + 3) ? c0 : 0.0f;
    }
    for (int k = 1; k <= KMAX; ++k) {
        float4 t = *(const float4*)(g_T + (size_t)k * NNq + base);
#pragma unroll
        for (int f = 0; f < NF; ++f) {
            float c = g_coef[k * NF + f];
            acc[f].x = fmaf(c, t.x, acc[f].x);
            acc[f].y = fmaf(c, t.y, acc[f].y);
            acc[f].z = fmaf(c, t.z, acc[f].z);
            acc[f].w = fmaf(c, t.w, acc[f].w);
        }
    }
#pragma unroll
    for (int f = 0; f < NF; ++f)
        *(float4*)(out + (size_t)f * NNq + base) = acc[f];
}

// ---------------------------------------------------------------------------
extern "C" void kernel_launch(void* const* d_in, const int* in_sizes, int n_in,
                              void* d_out, int out_size)
{
    const float* L = (const float*)d_in[0];
    float* out = (float*)d_out;

    cudaFuncSetAttribute(cheb_mma_kernel,
                         cudaFuncAttributeMaxDynamicSharedMemorySize, SMEM_BYTES);

    coef_kernel<<<1, 160>>>();
    prep_kernel<<<(int)(NNq / 256), 256>>>(L);

    dim3 grid(NV / BN, NV / BM);   // 32 x 32
    for (int k = 2; k <= KMAX; ++k)
        cheb_mma_kernel<<<grid, 256, SMEM_BYTES>>>(k);

    reduce_kernel<<<(int)(NNq / 4 / 256), 256>>>(out);
}

// round 11
// speedup vs baseline: 1.7115x; 1.0078x over previous
#include <cuda_runtime.h>
#include <cuda_bf16.h>
#include <cstdint>

#define NV 4096
#define NNq 16777216ULL          // NV*NV
#define NF 4
#define KMAX 7                   // truncation (calibrated: rel_err ~3.4e-4, ~3x margin)
#define NCOEF 33

#define BM 128
#define BN 128
#define BK 32
#define NCHUNK (NV / BK)         // 128
#define REGION_BYTES 8192        // 128 rows x 64B (swizzled, no pad)
#define BUF_BYTES (4 * REGION_BYTES)   // Ah, Al, Bh, Bl = 32768
#define NSTAGE 3
#define SMEM_BYTES (NSTAGE * BUF_BYTES)  // 98304 -> 2 CTAs/SM (192KB/SM)

// 64B-row swizzle: bits[5:4] ^= bits[8:7]; conflict-free ldmatrix at 64B stride
#define SWZ64(x) ((x) ^ (((x) >> 3) & 0x30))

// ---------------------------------------------------------------------------
// Static device scratch
// ---------------------------------------------------------------------------
__device__ float g_T[(KMAX + 1) * NNq];       // T_0..T_KMAX fp32
__device__ __nv_bfloat16 g_Bh[2][NNq];        // bf16 hi split of T (ping-pong)
__device__ __nv_bfloat16 g_Bl[2][NNq];        // bf16 lo split of T
__device__ __nv_bfloat16 g_Ah[NNq];           // bf16 hi split of L
__device__ __nv_bfloat16 g_Al[NNq];           // bf16 lo split of L
__device__ float g_coef[NCOEF * NF];

// ---------------------------------------------------------------------------
// Helpers
// ---------------------------------------------------------------------------
__device__ __forceinline__ uint32_t s2u(const void* p) {
    uint32_t a;
    asm("{ .reg .u64 t; cvta.to.shared.u64 t, %1; cvt.u32.u64 %0, t; }"
        : "=r"(a) : "l"(p));
    return a;
}

__device__ __forceinline__ void cp16(uint32_t dst, const void* src) {
    asm volatile("cp.async.cg.shared.global [%0], [%1], 16;" :: "r"(dst), "l"(src));
}
#define CP_COMMIT() asm volatile("cp.async.commit_group;" ::: "memory")
#define CP_WAIT(n)  asm volatile("cp.async.wait_group %0;" :: "n"(n) : "memory")

__device__ __forceinline__ void ldm_x4(uint32_t* r, uint32_t addr) {
    asm volatile("ldmatrix.sync.aligned.m8n8.x4.shared.b16 {%0,%1,%2,%3}, [%4];"
                 : "=r"(r[0]), "=r"(r[1]), "=r"(r[2]), "=r"(r[3]) : "r"(addr));
}

__device__ __forceinline__ void mma_bf16(float* d, const uint32_t* a,
                                         uint32_t b0, uint32_t b1) {
    asm volatile(
        "mma.sync.aligned.m16n8k16.row.col.f32.bf16.bf16.f32 "
        "{%0,%1,%2,%3}, {%4,%5,%6,%7}, {%8,%9}, {%0,%1,%2,%3};"
        : "+f"(d[0]), "+f"(d[1]), "+f"(d[2]), "+f"(d[3])
        : "r"(a[0]), "r"(a[1]), "r"(a[2]), "r"(a[3]), "r"(b0), "r"(b1));
}

// ---------------------------------------------------------------------------
// Chebyshev coefficients (fp64); sqrt(N)=64 and 0.5*c0 folded in
// ---------------------------------------------------------------------------
__global__ void coef_kernel() {
    int t = threadIdx.x;
    if (t >= NCOEF * NF) return;
    int o = t >> 2, f = t & 3;
    const double taus[4] = {0.5, 1.0, 2.0, 4.0};
    const double PI = 3.14159265358979323846;
    double s = 0.0;
    for (int j = 0; j < NCOEF; j++) {
        double u = (j + 0.5) / (double)NCOEF;
        double x = cos(PI * u) + 1.0;
        s += cos(PI * (double)o * u) * exp(-taus[f] * x);
    }
    double c = (2.0 / (double)NCOEF) * s * 64.0;
    if (o == 0) c *= 0.5;
    g_coef[o * NF + f] = (float)c;
}

// ---------------------------------------------------------------------------
// Prep: T0 = I, T1 = L - I; bf16 hi/lo splits of L and T1
// ---------------------------------------------------------------------------
__global__ void prep_kernel(const float* __restrict__ L) {
    size_t idx = (size_t)blockIdx.x * 256 + threadIdx.x;
    int i = (int)(idx >> 12), j = (int)(idx & (NV - 1));
    float l = L[idx];
    float d = (i == j) ? 1.0f : 0.0f;
    float t1 = l - d;
    g_T[idx] = d;
    g_T[NNq + idx] = t1;
    __nv_bfloat16 ah = __float2bfloat16(l);
    g_Ah[idx] = ah;
    g_Al[idx] = __float2bfloat16(l - __bfloat162float(ah));
    __nv_bfloat16 bh = __float2bfloat16(t1);
    g_Bh[1][idx] = bh;
    g_Bl[1][idx] = __float2bfloat16(t1 - __bfloat162float(bh));
}

// ---------------------------------------------------------------------------
// Stage one K-chunk: regions 0=Ah, 1=Al, 2=Bh (rows of T = B^T), 3=Bl
// ---------------------------------------------------------------------------
__device__ __forceinline__ void load_chunk(
    uint32_t sb, int buf, int c, int i0, int j0, int tid,
    const __nv_bfloat16* __restrict__ Bh_in,
    const __nv_bfloat16* __restrict__ Bl_in)
{
    const int k0 = c * BK;
    const uint32_t base = sb + buf * BUF_BYTES;
#pragma unroll
    for (int it = 0; it < 8; ++it) {
        int u = tid + it * 256;              // 0..2047
        int reg = u >> 9;                    // 0..3
        int v = u & 511;
        int row = v >> 2, q = v & 3;
        const __nv_bfloat16* src;
        int grow;
        if (reg == 0)      { src = g_Ah;  grow = i0 + row; }
        else if (reg == 1) { src = g_Al;  grow = i0 + row; }
        else if (reg == 2) { src = Bh_in; grow = j0 + row; }
        else               { src = Bl_in; grow = j0 + row; }
        uint32_t off = reg * REGION_BYTES + SWZ64((uint32_t)(row * 64 + q * 16));
        cp16(base + off, src + (size_t)grow * NV + k0 + q * 8);
    }
}

// ---------------------------------------------------------------------------
// One Chebyshev step: acc = L @ T_{k-1} (3-term bf16 split HMMA), epilogue
// T_k = 2*acc - 2*T_{k-1} - T_{k-2}, plus bf16 hi/lo split of T_k.
// 3-stage pipeline, one barrier per chunk, 2 CTAs/SM.
// MMA issue order is TERM-MAJOR: same-accumulator RAW spacing 8 (was 2).
// Per-accumulator term order stays hh -> hl -> lh (bitwise-identical result).
// ---------------------------------------------------------------------------
__global__ void __launch_bounds__(256, 2)
cheb_mma_kernel(int k)
{
    extern __shared__ __align__(16) char smem[];
    const uint32_t sb = s2u(smem);
    const int tid = threadIdx.x;
    const int wid = tid >> 5;
    const int lane = tid & 31;
    const int warp_m = wid & 3;          // 4 warps over M (32 rows each)
    const int warp_n = wid >> 2;         // 2 warps over N (64 cols each)
    const int i0 = blockIdx.y * BM;
    const int j0 = blockIdx.x * BN;

    const float* __restrict__ Tcur = g_T + (size_t)(k - 1) * NNq;
    const float* __restrict__ Told = g_T + (size_t)(k - 2) * NNq;
    float* __restrict__ Tnew = g_T + (size_t)k * NNq;
    const __nv_bfloat16* __restrict__ Bh_in = g_Bh[(k - 1) & 1];
    const __nv_bfloat16* __restrict__ Bl_in = g_Bl[(k - 1) & 1];
    __nv_bfloat16* __restrict__ Bh_out = g_Bh[k & 1];
    __nv_bfloat16* __restrict__ Bl_out = g_Bl[k & 1];

    float acc[2][8][4];
#pragma unroll
    for (int a = 0; a < 2; ++a)
#pragma unroll
        for (int b = 0; b < 8; ++b)
#pragma unroll
            for (int d = 0; d < 4; ++d) acc[a][b][d] = 0.0f;

    // prologue: stage chunks 0 and 1
    load_chunk(sb, 0, 0, i0, j0, tid, Bh_in, Bl_in); CP_COMMIT();
    load_chunk(sb, 1, 1, i0, j0, tid, Bh_in, Bl_in); CP_COMMIT();

    for (int c = 0; c < NCHUNK; ++c) {
        if (c + 1 < NCHUNK) CP_WAIT(1); else CP_WAIT(0);   // chunk c resident
        __syncthreads();   // also: all warps done reading stage (c-1)%3

        if (c + 2 < NCHUNK) {
            load_chunk(sb, (c + 2) % NSTAGE, c + 2, i0, j0, tid, Bh_in, Bl_in);
            CP_COMMIT();
        }

        const uint32_t aBase = sb + (c % NSTAGE) * BUF_BYTES;
        const uint32_t bBase = aBase + 2 * REGION_BYTES;

#pragma unroll
        for (int s = 0; s < 2; ++s) {       // two k16 steps per BK=32 chunk
            uint32_t ah[2][4], al[2][4];
#pragma unroll
            for (int mt = 0; mt < 2; ++mt) {
                const int row = warp_m * 32 + mt * 16 + (lane & 15);
                const int col = s * 16 + (lane >> 4) * 8;
                const uint32_t off = SWZ64((uint32_t)(row * 64 + col * 2));
                ldm_x4(ah[mt], aBase + off);
                ldm_x4(al[mt], aBase + REGION_BYTES + off);
            }
#pragma unroll
            for (int pp = 0; pp < 2; ++pp) {   // B in pairs of n16 tiles
                uint32_t bh[2][4], bl[2][4];
#pragma unroll
                for (int p2 = 0; p2 < 2; ++p2) {
                    const int p = pp * 2 + p2;
                    const int n = warp_n * 64 + p * 16 + (lane & 7) + ((lane >> 4) & 1) * 8;
                    const int kk = s * 16 + ((lane >> 3) & 1) * 8;
                    const uint32_t off = SWZ64((uint32_t)(n * 64 + kk * 2));
                    ldm_x4(bh[p2], bBase + off);
                    ldm_x4(bl[p2], bBase + REGION_BYTES + off);
                }
                // term-major: each accumulator revisited every 8 MMAs
#pragma unroll
                for (int term = 0; term < 3; ++term)
#pragma unroll
                    for (int mt = 0; mt < 2; ++mt)
#pragma unroll
                        for (int p2 = 0; p2 < 2; ++p2) {
                            const int nt = 2 * (pp * 2 + p2);
                            const uint32_t* a = (term == 2) ? al[mt] : ah[mt];
                            const uint32_t* b = (term == 1) ? bl[p2] : bh[p2];
                            mma_bf16(acc[mt][nt + 0], a, b[0], b[1]);
                            mma_bf16(acc[mt][nt + 1], a, b[2], b[3]);
                        }
            }
        }
    }

    // ---- epilogue: Tnew = 2*acc - 2*Tcur - Told, bf16 split out
#pragma unroll
    for (int mt = 0; mt < 2; ++mt)
#pragma unroll
        for (int nt = 0; nt < 8; ++nt) {
            const int r0 = i0 + warp_m * 32 + mt * 16 + (lane >> 2);
            const int c0 = j0 + warp_n * 64 + nt * 8 + (lane & 3) * 2;
#pragma unroll
            for (int half = 0; half < 2; ++half) {
                const int r = r0 + half * 8;
                const size_t idx = (size_t)r * NV + c0;
                const float ax = acc[mt][nt][half * 2 + 0];
                const float ay = acc[mt][nt][half * 2 + 1];
                float2 tc = *(const float2*)(Tcur + idx);
                float2 to = *(const float2*)(Told + idx);
                float2 tn;
                tn.x = 2.0f * ax - 2.0f * tc.x - to.x;
                tn.y = 2.0f * ay - 2.0f * tc.y - to.y;
                *(float2*)(Tnew + idx) = tn;
                __nv_bfloat162 H, Lo;
                H.x = __float2bfloat16(tn.x);
                H.y = __float2bfloat16(tn.y);
                Lo.x = __float2bfloat16(tn.x - __bfloat162float(H.x));
                Lo.y = __float2bfloat16(tn.y - __bfloat162float(H.y));
                *(uint32_t*)(Bh_out + idx) = *reinterpret_cast<uint32_t*>(&H);
                *(uint32_t*)(Bl_out + idx) = *reinterpret_cast<uint32_t*>(&Lo);
            }
        }
}

// ---------------------------------------------------------------------------
// Final reduction: out[f] = c0[f]*I + sum_{k=1..KMAX} c_k[f] * T_k
// ---------------------------------------------------------------------------
__global__ void reduce_kernel(float* __restrict__ out) {
    size_t e = (size_t)blockIdx.x * 256 + threadIdx.x;
    size_t base = e * 4;
    int i = (int)(base >> 12);
    int jb = (int)(base & (NV - 1));
    float4 acc[NF];
#pragma unroll
    for (int f = 0; f < NF; ++f) {
        float c0 = g_coef[f];
        acc[f].x = (i == jb + 0) ? c0 : 0.0f;
        acc[f].y = (i == jb + 1) ? c0 : 0.0f;
        acc[f].z = (i == jb + 2) ? c0 : 0.0f;
        acc[f].w = (i == jb + 3) ? c0 : 0.0f;
    }
    for (int k = 1; k <= KMAX; ++k) {
        float4 t = *(const float4*)(g_T + (size_t)k * NNq + base);
#pragma unroll
        for (int f = 0; f < NF; ++f) {
            float c = g_coef[k * NF + f];
            acc[f].x = fmaf(c, t.x, acc[f].x);
            acc[f].y = fmaf(c, t.y, acc[f].y);
            acc[f].z = fmaf(c, t.z, acc[f].z);
            acc[f].w = fmaf(c, t.w, acc[f].w);
        }
    }
#pragma unroll
    for (int f = 0; f < NF; ++f)
        *(float4*)(out + (size_t)f * NNq + base) = acc[f];
}

// ---------------------------------------------------------------------------
extern "C" void kernel_launch(void* const* d_in, const int* in_sizes, int n_in,
                              void* d_out, int out_size)
{
    const float* L = (const float*)d_in[0];
    float* out = (float*)d_out;

    cudaFuncSetAttribute(cheb_mma_kernel,
                         cudaFuncAttributeMaxDynamicSharedMemorySize, SMEM_BYTES);

    coef_kernel<<<1, 160>>>();
    prep_kernel<<<(int)(NNq / 256), 256>>>(L);

    dim3 grid(NV / BN, NV / BM);   // 32 x 32
    for (int k = 2; k <= KMAX; ++k)
        cheb_mma_kernel<<<grid, 256, SMEM_BYTES>>>(k);

    reduce_kernel<<<(int)(NNq / 4 / 256), 256>>>(out);
}

// round 12
// speedup vs baseline: 2.8197x; 1.6475x over previous
#include <cuda_runtime.h>
#include <cuda_bf16.h>
#include <cstdint>

#define NV 4096
#define NNq 16777216ULL          // NV*NV
#define NF 4
#define KMAX 7                   // truncation (calibrated: rel_err ~3.4e-4, ~3x margin)
#define NCOEF 33

#define BM 128
#define BN 128
#define BK 32
#define NCHUNK (NV / BK)         // 128
#define NTILES 528               // upper-triangular 32x32 tile grid (i <= j)
#define REGION_BYTES 8192        // 128 rows x 64B (swizzled, no pad)
#define BUF_BYTES (4 * REGION_BYTES)   // Ah, Al, Bh, Bl = 32768
#define NSTAGE 3
#define SMEM_BYTES (NSTAGE * BUF_BYTES)  // 98304 -> 2 CTAs/SM (192KB/SM)
#define TPAD 132                 // fp32 transpose-buffer row stride (128+4)

// 64B-row swizzle: bits[5:4] ^= bits[8:7]; conflict-free ldmatrix at 64B stride
#define SWZ64(x) ((x) ^ (((x) >> 3) & 0x30))

// ---------------------------------------------------------------------------
// Static device scratch
// ---------------------------------------------------------------------------
__device__ float g_T[(KMAX + 1) * NNq];       // T_0..T_KMAX fp32 (all symmetric)
__device__ __nv_bfloat16 g_Bh[2][NNq];        // bf16 hi split of T (ping-pong)
__device__ __nv_bfloat16 g_Bl[2][NNq];        // bf16 lo split of T
__device__ __nv_bfloat16 g_Ah[NNq];           // bf16 hi split of L
__device__ __nv_bfloat16 g_Al[NNq];           // bf16 lo split of L
__device__ float g_coef[NCOEF * NF];

// ---------------------------------------------------------------------------
// Helpers
// ---------------------------------------------------------------------------
__device__ __forceinline__ uint32_t s2u(const void* p) {
    uint32_t a;
    asm("{ .reg .u64 t; cvta.to.shared.u64 t, %1; cvt.u32.u64 %0, t; }"
        : "=r"(a) : "l"(p));
    return a;
}

__device__ __forceinline__ void cp16(uint32_t dst, const void* src) {
    asm volatile("cp.async.cg.shared.global [%0], [%1], 16;" :: "r"(dst), "l"(src));
}
#define CP_COMMIT() asm volatile("cp.async.commit_group;" ::: "memory")
#define CP_WAIT(n)  asm volatile("cp.async.wait_group %0;" :: "n"(n) : "memory")

__device__ __forceinline__ void ldm_x4(uint32_t* r, uint32_t addr) {
    asm volatile("ldmatrix.sync.aligned.m8n8.x4.shared.b16 {%0,%1,%2,%3}, [%4];"
                 : "=r"(r[0]), "=r"(r[1]), "=r"(r[2]), "=r"(r[3]) : "r"(addr));
}

__device__ __forceinline__ void mma_bf16(float* d, const uint32_t* a,
                                         uint32_t b0, uint32_t b1) {
    asm volatile(
        "mma.sync.aligned.m16n8k16.row.col.f32.bf16.bf16.f32 "
        "{%0,%1,%2,%3}, {%4,%5,%6,%7}, {%8,%9}, {%0,%1,%2,%3};"
        : "+f"(d[0]), "+f"(d[1]), "+f"(d[2]), "+f"(d[3])
        : "r"(a[0]), "r"(a[1]), "r"(a[2]), "r"(a[3]), "r"(b0), "r"(b1));
}

// ---------------------------------------------------------------------------
// Chebyshev coefficients (fp64); sqrt(N)=64 and 0.5*c0 folded in
// ---------------------------------------------------------------------------
__global__ void coef_kernel() {
    int t = threadIdx.x;
    if (t >= NCOEF * NF) return;
    int o = t >> 2, f = t & 3;
    const double taus[4] = {0.5, 1.0, 2.0, 4.0};
    const double PI = 3.14159265358979323846;
    double s = 0.0;
    for (int j = 0; j < NCOEF; j++) {
        double u = (j + 0.5) / (double)NCOEF;
        double x = cos(PI * u) + 1.0;
        s += cos(PI * (double)o * u) * exp(-taus[f] * x);
    }
    double c = (2.0 / (double)NCOEF) * s * 64.0;
    if (o == 0) c *= 0.5;
    g_coef[o * NF + f] = (float)c;
}

// ---------------------------------------------------------------------------
// Prep: T0 = I, T1 = L - I; bf16 hi/lo splits of L and T1
// ---------------------------------------------------------------------------
__global__ void prep_kernel(const float* __restrict__ L) {
    size_t idx = (size_t)blockIdx.x * 256 + threadIdx.x;
    int i = (int)(idx >> 12), j = (int)(idx & (NV - 1));
    float l = L[idx];
    float d = (i == j) ? 1.0f : 0.0f;
    float t1 = l - d;
    g_T[idx] = d;
    g_T[NNq + idx] = t1;
    __nv_bfloat16 ah = __float2bfloat16(l);
    g_Ah[idx] = ah;
    g_Al[idx] = __float2bfloat16(l - __bfloat162float(ah));
    __nv_bfloat16 bh = __float2bfloat16(t1);
    g_Bh[1][idx] = bh;
    g_Bl[1][idx] = __float2bfloat16(t1 - __bfloat162float(bh));
}

// ---------------------------------------------------------------------------
// Stage one K-chunk: regions 0=Ah, 1=Al, 2=Bh (rows of T = B^T), 3=Bl
// ---------------------------------------------------------------------------
__device__ __forceinline__ void load_chunk(
    uint32_t sb, int buf, int c, int i0, int j0, int tid,
    const __nv_bfloat16* __restrict__ Bh_in,
    const __nv_bfloat16* __restrict__ Bl_in)
{
    const int k0 = c * BK;
    const uint32_t base = sb + buf * BUF_BYTES;
#pragma unroll
    for (int it = 0; it < 8; ++it) {
        int u = tid + it * 256;              // 0..2047
        int reg = u >> 9;                    // 0..3
        int v = u & 511;
        int row = v >> 2, q = v & 3;
        const __nv_bfloat16* src;
        int grow;
        if (reg == 0)      { src = g_Ah;  grow = i0 + row; }
        else if (reg == 1) { src = g_Al;  grow = i0 + row; }
        else if (reg == 2) { src = Bh_in; grow = j0 + row; }
        else               { src = Bl_in; grow = j0 + row; }
        uint32_t off = reg * REGION_BYTES + SWZ64((uint32_t)(row * 64 + q * 16));
        cp16(base + off, src + (size_t)grow * NV + k0 + q * 8);
    }
}

// ---------------------------------------------------------------------------
// One Chebyshev step on the UPPER-TRIANGULAR tiles only (T_k is symmetric):
//   acc = L @ T_{k-1} (3-term bf16 split HMMA) for tile (ti, tj), ti <= tj
//   T_k(i,j) = 2*acc - 2*T_{k-1}(i,j) - T_{k-2}(i,j); mirror T_k(j,i) = T_k(i,j)^T
// Transpose for the mirror goes through smem (stages are dead post-mainloop).
// ---------------------------------------------------------------------------
__global__ void __launch_bounds__(256, 2)
cheb_mma_kernel(int k)
{
    extern __shared__ __align__(16) char smem[];
    const uint32_t sb = s2u(smem);
    float* st = (float*)smem;            // transpose buffer (post-mainloop)
    const int tid = threadIdx.x;
    const int wid = tid >> 5;
    const int lane = tid & 31;
    const int warp_m = wid & 3;          // 4 warps over M (32 rows each)
    const int warp_n = wid >> 2;         // 2 warps over N (64 cols each)

    // triangular unrank: bid -> (ti, tj), ti <= tj
    int ti = 0, rem = blockIdx.x;
    while (rem >= 32 - ti) { rem -= 32 - ti; ++ti; }
    const int tj = ti + rem;
    const int i0 = ti * BM;
    const int j0 = tj * BN;

    const float* __restrict__ Tcur = g_T + (size_t)(k - 1) * NNq;
    const float* __restrict__ Told = g_T + (size_t)(k - 2) * NNq;
    float* __restrict__ Tnew = g_T + (size_t)k * NNq;
    const __nv_bfloat16* __restrict__ Bh_in = g_Bh[(k - 1) & 1];
    const __nv_bfloat16* __restrict__ Bl_in = g_Bl[(k - 1) & 1];
    __nv_bfloat16* __restrict__ Bh_out = g_Bh[k & 1];
    __nv_bfloat16* __restrict__ Bl_out = g_Bl[k & 1];

    float acc[2][8][4];
#pragma unroll
    for (int a = 0; a < 2; ++a)
#pragma unroll
        for (int b = 0; b < 8; ++b)
#pragma unroll
            for (int d = 0; d < 4; ++d) acc[a][b][d] = 0.0f;

    // prologue: stage chunks 0 and 1
    load_chunk(sb, 0, 0, i0, j0, tid, Bh_in, Bl_in); CP_COMMIT();
    load_chunk(sb, 1, 1, i0, j0, tid, Bh_in, Bl_in); CP_COMMIT();

    for (int c = 0; c < NCHUNK; ++c) {
        if (c + 1 < NCHUNK) CP_WAIT(1); else CP_WAIT(0);   // chunk c resident
        __syncthreads();   // also: all warps done reading stage (c-1)%3

        if (c + 2 < NCHUNK) {
            load_chunk(sb, (c + 2) % NSTAGE, c + 2, i0, j0, tid, Bh_in, Bl_in);
            CP_COMMIT();
        }

        const uint32_t aBase = sb + (c % NSTAGE) * BUF_BYTES;
        const uint32_t bBase = aBase + 2 * REGION_BYTES;

#pragma unroll
        for (int s = 0; s < 2; ++s) {       // two k16 steps per BK=32 chunk
            uint32_t ah[2][4], al[2][4];
#pragma unroll
            for (int mt = 0; mt < 2; ++mt) {
                const int row = warp_m * 32 + mt * 16 + (lane & 15);
                const int col = s * 16 + (lane >> 4) * 8;
                const uint32_t off = SWZ64((uint32_t)(row * 64 + col * 2));
                ldm_x4(ah[mt], aBase + off);
                ldm_x4(al[mt], aBase + REGION_BYTES + off);
            }
#pragma unroll
            for (int pp = 0; pp < 2; ++pp) {   // B in pairs of n16 tiles
                uint32_t bh[2][4], bl[2][4];
#pragma unroll
                for (int p2 = 0; p2 < 2; ++p2) {
                    const int p = pp * 2 + p2;
                    const int n = warp_n * 64 + p * 16 + (lane & 7) + ((lane >> 4) & 1) * 8;
                    const int kk = s * 16 + ((lane >> 3) & 1) * 8;
                    const uint32_t off = SWZ64((uint32_t)(n * 64 + kk * 2));
                    ldm_x4(bh[p2], bBase + off);
                    ldm_x4(bl[p2], bBase + REGION_BYTES + off);
                }
                // term-major: each accumulator revisited every 8 MMAs
#pragma unroll
                for (int term = 0; term < 3; ++term)
#pragma unroll
                    for (int mt = 0; mt < 2; ++mt)
#pragma unroll
                        for (int p2 = 0; p2 < 2; ++p2) {
                            const int nt = 2 * (pp * 2 + p2);
                            const uint32_t* a = (term == 2) ? al[mt] : ah[mt];
                            const uint32_t* b = (term == 1) ? bl[p2] : bh[p2];
                            mma_bf16(acc[mt][nt + 0], a, b[0], b[1]);
                            mma_bf16(acc[mt][nt + 1], a, b[2], b[3]);
                        }
            }
        }
    }

    // all warps past the mainloop before smem is repurposed
    __syncthreads();

    // ---- epilogue phase 1: block (ti,tj): Tnew = 2*acc - 2*Tcur - Told,
    //      bf16 split out, and stash transposed values into smem.
#pragma unroll
    for (int mt = 0; mt < 2; ++mt)
#pragma unroll
        for (int nt = 0; nt < 8; ++nt) {
            const int rl0 = warp_m * 32 + mt * 16 + (lane >> 2);
            const int cl = warp_n * 64 + nt * 8 + (lane & 3) * 2;
#pragma unroll
            for (int half = 0; half < 2; ++half) {
                const int rl = rl0 + half * 8;
                const size_t idx = (size_t)(i0 + rl) * NV + j0 + cl;
                const float ax = acc[mt][nt][half * 2 + 0];
                const float ay = acc[mt][nt][half * 2 + 1];
                float2 tc = *(const float2*)(Tcur + idx);
                float2 to = *(const float2*)(Told + idx);
                float2 tn;
                tn.x = 2.0f * ax - 2.0f * tc.x - to.x;
                tn.y = 2.0f * ay - 2.0f * tc.y - to.y;
                *(float2*)(Tnew + idx) = tn;
                __nv_bfloat162 H, Lo;
                H.x = __float2bfloat16(tn.x);
                H.y = __float2bfloat16(tn.y);
                Lo.x = __float2bfloat16(tn.x - __bfloat162float(H.x));
                Lo.y = __float2bfloat16(tn.y - __bfloat162float(H.y));
                *(uint32_t*)(Bh_out + idx) = *reinterpret_cast<uint32_t*>(&H);
                *(uint32_t*)(Bl_out + idx) = *reinterpret_cast<uint32_t*>(&Lo);
                if (ti != tj) {                       // stash transposed
                    st[cl * TPAD + rl] = tn.x;
                    st[(cl + 1) * TPAD + rl] = tn.y;
                }
            }
        }

    // ---- epilogue phase 2: mirror block (tj,ti) = transpose, coalesced
    if (ti != tj) {
        __syncthreads();
        for (int u = tid; u < 128 * 32; u += 256) {
            const int cl = u >> 5;              // original col 0..127
            const int r4 = (u & 31) * 4;        // original row, x4
            float4 v = *(const float4*)&st[cl * TPAD + r4];
            const size_t idx2 = (size_t)(j0 + cl) * NV + i0 + r4;
            *(float4*)(Tnew + idx2) = v;
            __nv_bfloat162 H01, H23, L01, L23;
            H01.x = __float2bfloat16(v.x);  H01.y = __float2bfloat16(v.y);
            H23.x = __float2bfloat16(v.z);  H23.y = __float2bfloat16(v.w);
            L01.x = __float2bfloat16(v.x - __bfloat162float(H01.x));
            L01.y = __float2bfloat16(v.y - __bfloat162float(H01.y));
            L23.x = __float2bfloat16(v.z - __bfloat162float(H23.x));
            L23.y = __float2bfloat16(v.w - __bfloat162float(H23.y));
            uint2 hv, lv;
            hv.x = *reinterpret_cast<uint32_t*>(&H01);
            hv.y = *reinterpret_cast<uint32_t*>(&H23);
            lv.x = *reinterpret_cast<uint32_t*>(&L01);
            lv.y = *reinterpret_cast<uint32_t*>(&L23);
            *(uint2*)(Bh_out + idx2) = hv;
            *(uint2*)(Bl_out + idx2) = lv;
        }
    }
}

// ---------------------------------------------------------------------------
// Final reduction: out[f] = c0[f]*I + sum_{k=1..KMAX} c_k[f] * T_k
// ---------------------------------------------------------------------------
__global__ void reduce_kernel(float* __restrict__ out) {
    size_t e = (size_t)blockIdx.x * 256 + threadIdx.x;
    size_t base = e * 4;
    int i = (int)(base >> 12);
    int jb = (int)(base & (NV - 1));
    float4 acc[NF];
#pragma unroll
    for (int f = 0; f < NF; ++f) {
        float c0 = g_coef[f];
        acc[f].x = (i == jb + 0) ? c0 : 0.0f;
        acc[f].y = (i == jb + 1) ? c0 : 0.0f;
        acc[f].z = (i == jb + 2) ? c0 : 0.0f;
        acc[f].w = (i == jb + 3) ? c0 : 0.0f;
    }
    for (int k = 1; k <= KMAX; ++k) {
        float4 t = *(const float4*)(g_T + (size_t)k * NNq + base);
#pragma unroll
        for (int f = 0; f < NF; ++f) {
            float c = g_coef[k * NF + f];
            acc[f].x = fmaf(c, t.x, acc[f].x);
            acc[f].y = fmaf(c, t.y, acc[f].y);
            acc[f].z = fmaf(c, t.z, acc[f].z);
            acc[f].w = fmaf(c, t.w, acc[f].w);
        }
    }
#pragma unroll
    for (int f = 0; f < NF; ++f)
        *(float4*)(out + (size_t)f * NNq + base) = acc[f];
}

// ---------------------------------------------------------------------------
extern "C" void kernel_launch(void* const* d_in, const int* in_sizes, int n_in,
                              void* d_out, int out_size)
{
    const float* L = (const float*)d_in[0];
    float* out = (float*)d_out;

    cudaFuncSetAttribute(cheb_mma_kernel,
                         cudaFuncAttributeMaxDynamicSharedMemorySize, SMEM_BYTES);

    coef_kernel<<<1, 160>>>();
    prep_kernel<<<(int)(NNq / 256), 256>>>(L);

    for (int k = 2; k <= KMAX; ++k)
        cheb_mma_kernel<<<NTILES, 256, SMEM_BYTES>>>(k);

    reduce_kernel<<<(int)(NNq / 4 / 256), 256>>>(out);
}

// round 14
// speedup vs baseline: 2.8373x; 1.0062x over previous
#include <cuda_runtime.h>
#include <cuda_bf16.h>
#include <cstdint>

#define NV 4096
#define NNq 16777216ULL          // NV*NV
#define NF 4
#define KMAX 7                   // truncation (calibrated: rel_err ~3.4e-4, ~3x margin)
#define NCOEF 33

#define BM 128
#define BN 128
#define BK 32
#define NCHUNK (NV / BK)         // 128
#define NTILES 528               // upper-triangular 32x32 tile grid (i <= j)
#define REGION_BYTES 8192        // 128 rows x 64B (swizzled, no pad)
#define BUF_BYTES (4 * REGION_BYTES)   // Ah, Al, Bh, Bl = 32768
#define NSTAGE 3
#define SMEM_BYTES (NSTAGE * BUF_BYTES)  // 98304 -> 2 CTAs/SM (192KB/SM)
#define TPAD 132                 // fp32 transpose-buffer row stride (128+4)

// reduce2 smem: 4 filters x 32 strip-cols x 132-padded rows of fp32
// RPITCH MUST be a multiple of 4 (float4 alignment of row starts): 132*4=528=33*16
#define RPITCH 132
#define RSMEM (4 * 32 * RPITCH * 4)    // 67584 bytes

// 64B-row swizzle: bits[5:4] ^= bits[8:7]; conflict-free ldmatrix at 64B stride
#define SWZ64(x) ((x) ^ (((x) >> 3) & 0x30))

// ---------------------------------------------------------------------------
// Static device scratch
// ---------------------------------------------------------------------------
__device__ float g_T[(KMAX + 1) * NNq];       // T_0..T_KMAX fp32 (upper-valid)
__device__ __nv_bfloat16 g_Bh[2][NNq];        // bf16 hi split of T (ping-pong)
__device__ __nv_bfloat16 g_Bl[2][NNq];        // bf16 lo split of T
__device__ __nv_bfloat16 g_Ah[NNq];           // bf16 hi split of L
__device__ __nv_bfloat16 g_Al[NNq];           // bf16 lo split of L
__device__ float g_coef[NCOEF * NF];

// ---------------------------------------------------------------------------
// Helpers
// ---------------------------------------------------------------------------
__device__ __forceinline__ uint32_t s2u(const void* p) {
    uint32_t a;
    asm("{ .reg .u64 t; cvta.to.shared.u64 t, %1; cvt.u32.u64 %0, t; }"
        : "=r"(a) : "l"(p));
    return a;
}

__device__ __forceinline__ void cp16(uint32_t dst, const void* src) {
    asm volatile("cp.async.cg.shared.global [%0], [%1], 16;" :: "r"(dst), "l"(src));
}
#define CP_COMMIT() asm volatile("cp.async.commit_group;" ::: "memory")
#define CP_WAIT(n)  asm volatile("cp.async.wait_group %0;" :: "n"(n) : "memory")

__device__ __forceinline__ void ldm_x4(uint32_t* r, uint32_t addr) {
    asm volatile("ldmatrix.sync.aligned.m8n8.x4.shared.b16 {%0,%1,%2,%3}, [%4];"
                 : "=r"(r[0]), "=r"(r[1]), "=r"(r[2]), "=r"(r[3]) : "r"(addr));
}

__device__ __forceinline__ void mma_bf16(float* d, const uint32_t* a,
                                         uint32_t b0, uint32_t b1) {
    asm volatile(
        "mma.sync.aligned.m16n8k16.row.col.f32.bf16.bf16.f32 "
        "{%0,%1,%2,%3}, {%4,%5,%6,%7}, {%8,%9}, {%0,%1,%2,%3};"
        : "+f"(d[0]), "+f"(d[1]), "+f"(d[2]), "+f"(d[3])
        : "r"(a[0]), "r"(a[1]), "r"(a[2]), "r"(a[3]), "r"(b0), "r"(b1));
}

// ---------------------------------------------------------------------------
// Chebyshev coefficients (fp64); sqrt(N)=64 and 0.5*c0 folded in
// ---------------------------------------------------------------------------
__global__ void coef_kernel() {
    int t = threadIdx.x;
    if (t >= NCOEF * NF) return;
    int o = t >> 2, f = t & 3;
    const double taus[4] = {0.5, 1.0, 2.0, 4.0};
    const double PI = 3.14159265358979323846;
    double s = 0.0;
    for (int j = 0; j < NCOEF; j++) {
        double u = (j + 0.5) / (double)NCOEF;
        double x = cos(PI * u) + 1.0;
        s += cos(PI * (double)o * u) * exp(-taus[f] * x);
    }
    double c = (2.0 / (double)NCOEF) * s * 64.0;
    if (o == 0) c *= 0.5;
    g_coef[o * NF + f] = (float)c;
}

// ---------------------------------------------------------------------------
// Prep: T0 = I, T1 = L - I; bf16 hi/lo splits of L and T1
// ---------------------------------------------------------------------------
__global__ void prep_kernel(const float* __restrict__ L) {
    size_t idx = (size_t)blockIdx.x * 256 + threadIdx.x;
    int i = (int)(idx >> 12), j = (int)(idx & (NV - 1));
    float l = L[idx];
    float d = (i == j) ? 1.0f : 0.0f;
    float t1 = l - d;
    g_T[idx] = d;
    g_T[NNq + idx] = t1;
    __nv_bfloat16 ah = __float2bfloat16(l);
    g_Ah[idx] = ah;
    g_Al[idx] = __float2bfloat16(l - __bfloat162float(ah));
    __nv_bfloat16 bh = __float2bfloat16(t1);
    g_Bh[1][idx] = bh;
    g_Bl[1][idx] = __float2bfloat16(t1 - __bfloat162float(bh));
}

// ---------------------------------------------------------------------------
// Stage one K-chunk: regions 0=Ah, 1=Al, 2=Bh (rows of T = B^T), 3=Bl
// ---------------------------------------------------------------------------
__device__ __forceinline__ void load_chunk(
    uint32_t sb, int buf, int c, int i0, int j0, int tid,
    const __nv_bfloat16* __restrict__ Bh_in,
    const __nv_bfloat16* __restrict__ Bl_in)
{
    const int k0 = c * BK;
    const uint32_t base = sb + buf * BUF_BYTES;
#pragma unroll
    for (int it = 0; it < 8; ++it) {
        int u = tid + it * 256;              // 0..2047
        int reg = u >> 9;                    // 0..3
        int v = u & 511;
        int row = v >> 2, q = v & 3;
        const __nv_bfloat16* src;
        int grow;
        if (reg == 0)      { src = g_Ah;  grow = i0 + row; }
        else if (reg == 1) { src = g_Al;  grow = i0 + row; }
        else if (reg == 2) { src = Bh_in; grow = j0 + row; }
        else               { src = Bl_in; grow = j0 + row; }
        uint32_t off = reg * REGION_BYTES + SWZ64((uint32_t)(row * 64 + q * 16));
        cp16(base + off, src + (size_t)grow * NV + k0 + q * 8);
    }
}

// ---------------------------------------------------------------------------
// One Chebyshev step on UPPER-TRIANGULAR tiles (T_k symmetric):
//   acc = L @ T_{k-1}; T_k = 2*acc - 2*T_{k-1} - T_{k-2}
// fp32 T_k stored UPPER ONLY (no reader needs the mirror).
// bf16 splits written both halves (next step's B reads full rows), except at
// k == KMAX where no successor exists: split + mirror skipped entirely.
// ---------------------------------------------------------------------------
__global__ void __launch_bounds__(256, 2)
cheb_mma_kernel(int k)
{
    extern __shared__ __align__(16) char smem[];
    const uint32_t sb = s2u(smem);
    float* st = (float*)smem;            // transpose buffer (post-mainloop)
    const int tid = threadIdx.x;
    const int wid = tid >> 5;
    const int lane = tid & 31;
    const int warp_m = wid & 3;          // 4 warps over M (32 rows each)
    const int warp_n = wid >> 2;         // 2 warps over N (64 cols each)

    // triangular unrank: bid -> (ti, tj), ti <= tj
    int ti = 0, rem = blockIdx.x;
    while (rem >= 32 - ti) { rem -= 32 - ti; ++ti; }
    const int tj = ti + rem;
    const int i0 = ti * BM;
    const int j0 = tj * BN;

    const float* __restrict__ Tcur = g_T + (size_t)(k - 1) * NNq;
    const float* __restrict__ Told = g_T + (size_t)(k - 2) * NNq;
    float* __restrict__ Tnew = g_T + (size_t)k * NNq;
    const __nv_bfloat16* __restrict__ Bh_in = g_Bh[(k - 1) & 1];
    const __nv_bfloat16* __restrict__ Bl_in = g_Bl[(k - 1) & 1];
    __nv_bfloat16* __restrict__ Bh_out = g_Bh[k & 1];
    __nv_bfloat16* __restrict__ Bl_out = g_Bl[k & 1];
    const bool need_split = (k < KMAX);

    float acc[2][8][4];
#pragma unroll
    for (int a = 0; a < 2; ++a)
#pragma unroll
        for (int b = 0; b < 8; ++b)
#pragma unroll
            for (int d = 0; d < 4; ++d) acc[a][b][d] = 0.0f;

    // prologue: stage chunks 0 and 1
    load_chunk(sb, 0, 0, i0, j0, tid, Bh_in, Bl_in); CP_COMMIT();
    load_chunk(sb, 1, 1, i0, j0, tid, Bh_in, Bl_in); CP_COMMIT();

    for (int c = 0; c < NCHUNK; ++c) {
        if (c + 1 < NCHUNK) CP_WAIT(1); else CP_WAIT(0);   // chunk c resident
        __syncthreads();   // also: all warps done reading stage (c-1)%3

        if (c + 2 < NCHUNK) {
            load_chunk(sb, (c + 2) % NSTAGE, c + 2, i0, j0, tid, Bh_in, Bl_in);
            CP_COMMIT();
        }

        const uint32_t aBase = sb + (c % NSTAGE) * BUF_BYTES;
        const uint32_t bBase = aBase + 2 * REGION_BYTES;

#pragma unroll
        for (int s = 0; s < 2; ++s) {       // two k16 steps per BK=32 chunk
            uint32_t ah[2][4], al[2][4];
#pragma unroll
            for (int mt = 0; mt < 2; ++mt) {
                const int row = warp_m * 32 + mt * 16 + (lane & 15);
                const int col = s * 16 + (lane >> 4) * 8;
                const uint32_t off = SWZ64((uint32_t)(row * 64 + col * 2));
                ldm_x4(ah[mt], aBase + off);
                ldm_x4(al[mt], aBase + REGION_BYTES + off);
            }
#pragma unroll
            for (int pp = 0; pp < 2; ++pp) {   // B in pairs of n16 tiles
                uint32_t bh[2][4], bl[2][4];
#pragma unroll
                for (int p2 = 0; p2 < 2; ++p2) {
                    const int p = pp * 2 + p2;
                    const int n = warp_n * 64 + p * 16 + (lane & 7) + ((lane >> 4) & 1) * 8;
                    const int kk = s * 16 + ((lane >> 3) & 1) * 8;
                    const uint32_t off = SWZ64((uint32_t)(n * 64 + kk * 2));
                    ldm_x4(bh[p2], bBase + off);
                    ldm_x4(bl[p2], bBase + REGION_BYTES + off);
                }
                // term-major: each accumulator revisited every 8 MMAs
#pragma unroll
                for (int term = 0; term < 3; ++term)
#pragma unroll
                    for (int mt = 0; mt < 2; ++mt)
#pragma unroll
                        for (int p2 = 0; p2 < 2; ++p2) {
                            const int nt = 2 * (pp * 2 + p2);
                            const uint32_t* a = (term == 2) ? al[mt] : ah[mt];
                            const uint32_t* b = (term == 1) ? bl[p2] : bh[p2];
                            mma_bf16(acc[mt][nt + 0], a, b[0], b[1]);
                            mma_bf16(acc[mt][nt + 1], a, b[2], b[3]);
                        }
            }
        }
    }

    // all warps past the mainloop before smem is repurposed
    __syncthreads();

    // ---- epilogue phase 1: Tnew (fp32, upper block only), bf16 split
    //      (only if k < KMAX), stash for mirror (only if needed).
#pragma unroll
    for (int mt = 0; mt < 2; ++mt)
#pragma unroll
        for (int nt = 0; nt < 8; ++nt) {
            const int rl0 = warp_m * 32 + mt * 16 + (lane >> 2);
            const int cl = warp_n * 64 + nt * 8 + (lane & 3) * 2;
#pragma unroll
            for (int half = 0; half < 2; ++half) {
                const int rl = rl0 + half * 8;
                const size_t idx = (size_t)(i0 + rl) * NV + j0 + cl;
                const float ax = acc[mt][nt][half * 2 + 0];
                const float ay = acc[mt][nt][half * 2 + 1];
                float2 tc = *(const float2*)(Tcur + idx);
                float2 to = *(const float2*)(Told + idx);
                float2 tn;
                tn.x = 2.0f * ax - 2.0f * tc.x - to.x;
                tn.y = 2.0f * ay - 2.0f * tc.y - to.y;
                *(float2*)(Tnew + idx) = tn;
                if (need_split) {
                    __nv_bfloat162 H, Lo;
                    H.x = __float2bfloat16(tn.x);
                    H.y = __float2bfloat16(tn.y);
                    Lo.x = __float2bfloat16(tn.x - __bfloat162float(H.x));
                    Lo.y = __float2bfloat16(tn.y - __bfloat162float(H.y));
                    *(uint32_t*)(Bh_out + idx) = *reinterpret_cast<uint32_t*>(&H);
                    *(uint32_t*)(Bl_out + idx) = *reinterpret_cast<uint32_t*>(&Lo);
                    if (ti != tj) {                   // stash for bf16 mirror
                        st[cl * TPAD + rl] = tn.x;
                        st[(cl + 1) * TPAD + rl] = tn.y;
                    }
                }
            }
        }

    // ---- epilogue phase 2: bf16 mirror block (tj,ti), coalesced.
    //      (fp32 mirror intentionally NOT written — nothing reads it.)
    if (ti != tj && need_split) {
        __syncthreads();
        for (int u = tid; u < 128 * 32; u += 256) {
            const int cl = u >> 5;              // original col 0..127
            const int r4 = (u & 31) * 4;        // original row, x4
            float4 v = *(const float4*)&st[cl * TPAD + r4];
            const size_t idx2 = (size_t)(j0 + cl) * NV + i0 + r4;
            __nv_bfloat162 H01, H23, L01, L23;
            H01.x = __float2bfloat16(v.x);  H01.y = __float2bfloat16(v.y);
            H23.x = __float2bfloat16(v.z);  H23.y = __float2bfloat16(v.w);
            L01.x = __float2bfloat16(v.x - __bfloat162float(H01.x));
            L01.y = __float2bfloat16(v.y - __bfloat162float(H01.y));
            L23.x = __float2bfloat16(v.z - __bfloat162float(H23.x));
            L23.y = __float2bfloat16(v.w - __bfloat162float(H23.y));
            uint2 hv, lv;
            hv.x = *reinterpret_cast<uint32_t*>(&H01);
            hv.y = *reinterpret_cast<uint32_t*>(&H23);
            lv.x = *reinterpret_cast<uint32_t*>(&L01);
            lv.y = *reinterpret_cast<uint32_t*>(&L23);
            *(uint2*)(Bh_out + idx2) = hv;
            *(uint2*)(Bl_out + idx2) = lv;
        }
    }
}

// ---------------------------------------------------------------------------
// Reduce v2 (tile-based, upper-only reads):
//   out[f] = c0[f]*I + sum_{k=1..KMAX} c_k[f] * T_k
// For tile (ti,tj): compute 4 filter sums on the upper block (direct coalesced
// writes) and, for ti != tj, mirror via smem transpose in 4 column strips.
// ---------------------------------------------------------------------------
__global__ void __launch_bounds__(256, 2)
reduce2_kernel(float* __restrict__ out)
{
    extern __shared__ float sm[];        // [4][32][RPITCH]
    const int tid = threadIdx.x;

    int ti = 0, rem = blockIdx.x;
    while (rem >= 32 - ti) { rem -= 32 - ti; ++ti; }
    const int tj = ti + rem;
    const int i0 = ti * BM;
    const int j0 = tj * BN;

    // coefficients in registers
    float cf[KMAX + 1][NF];
#pragma unroll
    for (int k = 0; k <= KMAX; ++k)
#pragma unroll
        for (int f = 0; f < NF; ++f) cf[k][f] = g_coef[k * NF + f];

    for (int s = 0; s < 4; ++s) {        // 4 strips of 32 cols
#pragma unroll
        for (int it = 0; it < 4; ++it) { // 1024 float4 per strip / 256 threads
            const int idx = it * 256 + tid;
            const int row = idx >> 3;            // 0..127
            const int c4 = idx & 7;              // float4 index within strip
            const int colg = j0 + s * 32 + c4 * 4;
            const size_t base = (size_t)(i0 + row) * NV + colg;

            float4 a0, a1, a2, a3;
            a0.x = a0.y = a0.z = a0.w = 0.0f; a1 = a0; a2 = a0; a3 = a0;
            // identity term on diagonal positions
            const int d = (i0 + row) - colg;     // matches col e when d == e
            if (d >= 0 && d < 4) {
                float* p0 = &a0.x; float* p1 = &a1.x;
                float* p2 = &a2.x; float* p3 = &a3.x;
                p0[d] += cf[0][0]; p1[d] += cf[0][1];
                p2[d] += cf[0][2]; p3[d] += cf[0][3];
            }
#pragma unroll
            for (int k = 1; k <= KMAX; ++k) {
                float4 t = *(const float4*)(g_T + (size_t)k * NNq + base);
                a0.x = fmaf(cf[k][0], t.x, a0.x); a0.y = fmaf(cf[k][0], t.y, a0.y);
                a0.z = fmaf(cf[k][0], t.z, a0.z); a0.w = fmaf(cf[k][0], t.w, a0.w);
                a1.x = fmaf(cf[k][1], t.x, a1.x); a1.y = fmaf(cf[k][1], t.y, a1.y);
                a1.z = fmaf(cf[k][1], t.z, a1.z); a1.w = fmaf(cf[k][1], t.w, a1.w);
                a2.x = fmaf(cf[k][2], t.x, a2.x); a2.y = fmaf(cf[k][2], t.y, a2.y);
                a2.z = fmaf(cf[k][2], t.z, a2.z); a2.w = fmaf(cf[k][2], t.w, a2.w);
                a3.x = fmaf(cf[k][3], t.x, a3.x); a3.y = fmaf(cf[k][3], t.y, a3.y);
                a3.z = fmaf(cf[k][3], t.z, a3.z); a3.w = fmaf(cf[k][3], t.w, a3.w);
            }
            *(float4*)(out + 0 * NNq + base) = a0;
            *(float4*)(out + 1 * NNq + base) = a1;
            *(float4*)(out + 2 * NNq + base) = a2;
            *(float4*)(out + 3 * NNq + base) = a3;

            if (ti != tj) {              // stash for transposed mirror
                const int cb = c4 * 4;   // col-in-strip base
                float* v[4] = {&a0.x, &a1.x, &a2.x, &a3.x};
#pragma unroll
                for (int f = 0; f < NF; ++f) {
                    float* base_f = sm + f * (32 * RPITCH);
#pragma unroll
                    for (int e = 0; e < 4; ++e)
                        base_f[(cb + e) * RPITCH + row] = v[f][e];
                }
            }
        }
        if (ti != tj) {
            __syncthreads();
#pragma unroll
            for (int f = 0; f < NF; ++f) {
                const float* base_f = sm + f * (32 * RPITCH);
                for (int u = tid; u < 32 * 32; u += 256) {
                    const int cl = u >> 5;           // strip col 0..31
                    const int r4 = (u & 31) * 4;     // original row, x4
                    float4 v = *(const float4*)&base_f[cl * RPITCH + r4];
                    *(float4*)(out + (size_t)f * NNq
                               + (size_t)(j0 + s * 32 + cl) * NV + i0 + r4) = v;
                }
            }
            __syncthreads();
        }
    }
}

// ---------------------------------------------------------------------------
extern "C" void kernel_launch(void* const* d_in, const int* in_sizes, int n_in,
                              void* d_out, int out_size)
{
    const float* L = (const float*)d_in[0];
    float* out = (float*)d_out;

    cudaFuncSetAttribute(cheb_mma_kernel,
                         cudaFuncAttributeMaxDynamicSharedMemorySize, SMEM_BYTES);
    cudaFuncSetAttribute(reduce2_kernel,
                         cudaFuncAttributeMaxDynamicSharedMemorySize, RSMEM);

    coef_kernel<<<1, 160>>>();
    prep_kernel<<<(int)(NNq / 256), 256>>>(L);

    for (int k = 2; k <= KMAX; ++k)
        cheb_mma_kernel<<<NTILES, 256, SMEM_BYTES>>>(k);

    reduce2_kernel<<<NTILES, 256, RSMEM>>>(out);
}

// round 15
// speedup vs baseline: 2.8380x; 1.0003x over previous
#include <cuda_runtime.h>
#include <cuda_bf16.h>
#include <cstdint>

#define NV 4096
#define NNq 16777216ULL          // NV*NV
#define NF 4
#define KMAX 7                   // truncation (calibrated: rel_err ~3.4e-4, ~3x margin)
#define NCOEF 33

#define BM 128
#define BN 128
#define BK 32
#define NCHUNK (NV / BK)         // 128
#define NTILES 528               // upper-triangular 32x32 tile grid (i <= j)
#define REGION_BYTES 8192        // 128 rows x 64B (swizzled, no pad)
#define BUF_BYTES (4 * REGION_BYTES)   // Ah, Al, Bh, Bl = 32768
#define NSTAGE 3
#define SMEM_BYTES (NSTAGE * BUF_BYTES)  // 98304 -> 2 CTAs/SM (192KB/SM)
#define TPAD 132                 // fp32 transpose-buffer row stride (128+4)

// reduce2 smem: 4 filters x 32 strip-cols x 132-padded rows of fp32
// RPITCH MUST be a multiple of 4 (float4 alignment of row starts): 132*4=528=33*16
#define RPITCH 132
#define RSMEM (4 * 32 * RPITCH * 4)    // 67584 bytes

// 64B-row swizzle: bits[5:4] ^= bits[8:7]; conflict-free ldmatrix at 64B stride
#define SWZ64(x) ((x) ^ (((x) >> 3) & 0x30))

// ---------------------------------------------------------------------------
// Static device scratch
// ---------------------------------------------------------------------------
__device__ float g_T[(KMAX + 1) * NNq];       // T_0..T_KMAX fp32 (upper-valid)
__device__ __nv_bfloat16 g_Bh[2][NNq];        // bf16 hi split of T (ping-pong)
__device__ __nv_bfloat16 g_Bl[2][NNq];        // bf16 lo split of T
__device__ __nv_bfloat16 g_Ah[NNq];           // bf16 hi split of L
__device__ __nv_bfloat16 g_Al[NNq];           // bf16 lo split of L
__device__ float g_coef[NCOEF * NF];

// ---------------------------------------------------------------------------
// Helpers
// ---------------------------------------------------------------------------
__device__ __forceinline__ uint32_t s2u(const void* p) {
    uint32_t a;
    asm("{ .reg .u64 t; cvta.to.shared.u64 t, %1; cvt.u32.u64 %0, t; }"
        : "=r"(a) : "l"(p));
    return a;
}

__device__ __forceinline__ void cp16(uint32_t dst, const void* src) {
    asm volatile("cp.async.cg.shared.global [%0], [%1], 16;" :: "r"(dst), "l"(src));
}
#define CP_COMMIT() asm volatile("cp.async.commit_group;" ::: "memory")
#define CP_WAIT(n)  asm volatile("cp.async.wait_group %0;" :: "n"(n) : "memory")

__device__ __forceinline__ void ldm_x4(uint32_t* r, uint32_t addr) {
    asm volatile("ldmatrix.sync.aligned.m8n8.x4.shared.b16 {%0,%1,%2,%3}, [%4];"
                 : "=r"(r[0]), "=r"(r[1]), "=r"(r[2]), "=r"(r[3]) : "r"(addr));
}

__device__ __forceinline__ void mma_bf16(float* d, const uint32_t* a,
                                         uint32_t b0, uint32_t b1) {
    asm volatile(
        "mma.sync.aligned.m16n8k16.row.col.f32.bf16.bf16.f32 "
        "{%0,%1,%2,%3}, {%4,%5,%6,%7}, {%8,%9}, {%0,%1,%2,%3};"
        : "+f"(d[0]), "+f"(d[1]), "+f"(d[2]), "+f"(d[3])
        : "r"(a[0]), "r"(a[1]), "r"(a[2]), "r"(a[3]), "r"(b0), "r"(b1));
}

// ---------------------------------------------------------------------------
// Chebyshev coefficients (fp64); sqrt(N)=64 and 0.5*c0 folded in
// ---------------------------------------------------------------------------
__global__ void coef_kernel() {
    int t = threadIdx.x;
    if (t >= NCOEF * NF) return;
    int o = t >> 2, f = t & 3;
    const double taus[4] = {0.5, 1.0, 2.0, 4.0};
    const double PI = 3.14159265358979323846;
    double s = 0.0;
    for (int j = 0; j < NCOEF; j++) {
        double u = (j + 0.5) / (double)NCOEF;
        double x = cos(PI * u) + 1.0;
        s += cos(PI * (double)o * u) * exp(-taus[f] * x);
    }
    double c = (2.0 / (double)NCOEF) * s * 64.0;
    if (o == 0) c *= 0.5;
    g_coef[o * NF + f] = (float)c;
}

// ---------------------------------------------------------------------------
// Prep: T0 = I, T1 = L - I; bf16 hi/lo splits of L and T1
// ---------------------------------------------------------------------------
__global__ void prep_kernel(const float* __restrict__ L) {
    size_t idx = (size_t)blockIdx.x * 256 + threadIdx.x;
    int i = (int)(idx >> 12), j = (int)(idx & (NV - 1));
    float l = L[idx];
    float d = (i == j) ? 1.0f : 0.0f;
    float t1 = l - d;
    g_T[idx] = d;
    g_T[NNq + idx] = t1;
    __nv_bfloat16 ah = __float2bfloat16(l);
    g_Ah[idx] = ah;
    g_Al[idx] = __float2bfloat16(l - __bfloat162float(ah));
    __nv_bfloat16 bh = __float2bfloat16(t1);
    g_Bh[1][idx] = bh;
    g_Bl[1][idx] = __float2bfloat16(t1 - __bfloat162float(bh));
}

// ---------------------------------------------------------------------------
// Stage one K-chunk: regions 0=Ah, 1=Al, 2=Bh (rows of T = B^T), 3=Bl
// ---------------------------------------------------------------------------
__device__ __forceinline__ void load_chunk(
    uint32_t sb, int buf, int c, int i0, int j0, int tid,
    const __nv_bfloat16* __restrict__ Bh_in,
    const __nv_bfloat16* __restrict__ Bl_in)
{
    const int k0 = c * BK;
    const uint32_t base = sb + buf * BUF_BYTES;
#pragma unroll
    for (int it = 0; it < 8; ++it) {
        int u = tid + it * 256;              // 0..2047
        int reg = u >> 9;                    // 0..3
        int v = u & 511;
        int row = v >> 2, q = v & 3;
        const __nv_bfloat16* src;
        int grow;
        if (reg == 0)      { src = g_Ah;  grow = i0 + row; }
        else if (reg == 1) { src = g_Al;  grow = i0 + row; }
        else if (reg == 2) { src = Bh_in; grow = j0 + row; }
        else               { src = Bl_in; grow = j0 + row; }
        uint32_t off = reg * REGION_BYTES + SWZ64((uint32_t)(row * 64 + q * 16));
        cp16(base + off, src + (size_t)grow * NV + k0 + q * 8);
    }
}

// ---------------------------------------------------------------------------
// One Chebyshev step on UPPER-TRIANGULAR tiles (T_k symmetric):
//   acc = L @ T_{k-1}; T_k = 2*acc - 2*T_{k-1} - T_{k-2}
// fp32 T_k stored UPPER ONLY (no reader needs the mirror).
// bf16 splits written both halves (next step's B reads full rows), except at
// k == KMAX where no successor exists: split + mirror skipped entirely.
// ---------------------------------------------------------------------------
__global__ void __launch_bounds__(256, 2)
cheb_mma_kernel(int k)
{
    extern __shared__ __align__(16) char smem[];
    const uint32_t sb = s2u(smem);
    float* st = (float*)smem;            // transpose buffer (post-mainloop)
    const int tid = threadIdx.x;
    const int wid = tid >> 5;
    const int lane = tid & 31;
    const int warp_m = wid & 3;          // 4 warps over M (32 rows each)
    const int warp_n = wid >> 2;         // 2 warps over N (64 cols each)

    // triangular unrank: bid -> (ti, tj), ti <= tj
    int ti = 0, rem = blockIdx.x;
    while (rem >= 32 - ti) { rem -= 32 - ti; ++ti; }
    const int tj = ti + rem;
    const int i0 = ti * BM;
    const int j0 = tj * BN;

    const float* __restrict__ Tcur = g_T + (size_t)(k - 1) * NNq;
    const float* __restrict__ Told = g_T + (size_t)(k - 2) * NNq;
    float* __restrict__ Tnew = g_T + (size_t)k * NNq;
    const __nv_bfloat16* __restrict__ Bh_in = g_Bh[(k - 1) & 1];
    const __nv_bfloat16* __restrict__ Bl_in = g_Bl[(k - 1) & 1];
    __nv_bfloat16* __restrict__ Bh_out = g_Bh[k & 1];
    __nv_bfloat16* __restrict__ Bl_out = g_Bl[k & 1];
    const bool need_split = (k < KMAX);

    float acc[2][8][4];
#pragma unroll
    for (int a = 0; a < 2; ++a)
#pragma unroll
        for (int b = 0; b < 8; ++b)
#pragma unroll
            for (int d = 0; d < 4; ++d) acc[a][b][d] = 0.0f;

    // prologue: stage chunks 0 and 1
    load_chunk(sb, 0, 0, i0, j0, tid, Bh_in, Bl_in); CP_COMMIT();
    load_chunk(sb, 1, 1, i0, j0, tid, Bh_in, Bl_in); CP_COMMIT();

    for (int c = 0; c < NCHUNK; ++c) {
        if (c + 1 < NCHUNK) CP_WAIT(1); else CP_WAIT(0);   // chunk c resident
        __syncthreads();   // also: all warps done reading stage (c-1)%3

        if (c + 2 < NCHUNK) {
            load_chunk(sb, (c + 2) % NSTAGE, c + 2, i0, j0, tid, Bh_in, Bl_in);
            CP_COMMIT();
        }

        const uint32_t aBase = sb + (c % NSTAGE) * BUF_BYTES;
        const uint32_t bBase = aBase + 2 * REGION_BYTES;

#pragma unroll
        for (int s = 0; s < 2; ++s) {       // two k16 steps per BK=32 chunk
            uint32_t ah[2][4], al[2][4];
#pragma unroll
            for (int mt = 0; mt < 2; ++mt) {
                const int row = warp_m * 32 + mt * 16 + (lane & 15);
                const int col = s * 16 + (lane >> 4) * 8;
                const uint32_t off = SWZ64((uint32_t)(row * 64 + col * 2));
                ldm_x4(ah[mt], aBase + off);
                ldm_x4(al[mt], aBase + REGION_BYTES + off);
            }
#pragma unroll
            for (int pp = 0; pp < 2; ++pp) {   // B in pairs of n16 tiles
                uint32_t bh[2][4], bl[2][4];
#pragma unroll
                for (int p2 = 0; p2 < 2; ++p2) {
                    const int p = pp * 2 + p2;
                    const int n = warp_n * 64 + p * 16 + (lane & 7) + ((lane >> 4) & 1) * 8;
                    const int kk = s * 16 + ((lane >> 3) & 1) * 8;
                    const uint32_t off = SWZ64((uint32_t)(n * 64 + kk * 2));
                    ldm_x4(bh[p2], bBase + off);
                    ldm_x4(bl[p2], bBase + REGION_BYTES + off);
                }
                // term-major: each accumulator revisited every 8 MMAs
#pragma unroll
                for (int term = 0; term < 3; ++term)
#pragma unroll
                    for (int mt = 0; mt < 2; ++mt)
#pragma unroll
                        for (int p2 = 0; p2 < 2; ++p2) {
                            const int nt = 2 * (pp * 2 + p2);
                            const uint32_t* a = (term == 2) ? al[mt] : ah[mt];
                            const uint32_t* b = (term == 1) ? bl[p2] : bh[p2];
                            mma_bf16(acc[mt][nt + 0], a, b[0], b[1]);
                            mma_bf16(acc[mt][nt + 1], a, b[2], b[3]);
                        }
            }
        }
    }

    // all warps past the mainloop before smem is repurposed
    __syncthreads();

    // ---- epilogue phase 1: Tnew (fp32, upper block only), bf16 split
    //      (only if k < KMAX), stash for mirror (only if needed).
#pragma unroll
    for (int mt = 0; mt < 2; ++mt)
#pragma unroll
        for (int nt = 0; nt < 8; ++nt) {
            const int rl0 = warp_m * 32 + mt * 16 + (lane >> 2);
            const int cl = warp_n * 64 + nt * 8 + (lane & 3) * 2;
#pragma unroll
            for (int half = 0; half < 2; ++half) {
                const int rl = rl0 + half * 8;
                const size_t idx = (size_t)(i0 + rl) * NV + j0 + cl;
                const float ax = acc[mt][nt][half * 2 + 0];
                const float ay = acc[mt][nt][half * 2 + 1];
                float2 tc = *(const float2*)(Tcur + idx);
                float2 to = *(const float2*)(Told + idx);
                float2 tn;
                tn.x = 2.0f * ax - 2.0f * tc.x - to.x;
                tn.y = 2.0f * ay - 2.0f * tc.y - to.y;
                *(float2*)(Tnew + idx) = tn;
                if (need_split) {
                    __nv_bfloat162 H, Lo;
                    H.x = __float2bfloat16(tn.x);
                    H.y = __float2bfloat16(tn.y);
                    Lo.x = __float2bfloat16(tn.x - __bfloat162float(H.x));
                    Lo.y = __float2bfloat16(tn.y - __bfloat162float(H.y));
                    *(uint32_t*)(Bh_out + idx) = *reinterpret_cast<uint32_t*>(&H);
                    *(uint32_t*)(Bl_out + idx) = *reinterpret_cast<uint32_t*>(&Lo);
                    if (ti != tj) {                   // stash for bf16 mirror
                        st[cl * TPAD + rl] = tn.x;
                        st[(cl + 1) * TPAD + rl] = tn.y;
                    }
                }
            }
        }

    // ---- epilogue phase 2: bf16 mirror block (tj,ti), coalesced.
    //      (fp32 mirror intentionally NOT written — nothing reads it.)
    if (ti != tj && need_split) {
        __syncthreads();
        for (int u = tid; u < 128 * 32; u += 256) {
            const int cl = u >> 5;              // original col 0..127
            const int r4 = (u & 31) * 4;        // original row, x4
            float4 v = *(const float4*)&st[cl * TPAD + r4];
            const size_t idx2 = (size_t)(j0 + cl) * NV + i0 + r4;
            __nv_bfloat162 H01, H23, L01, L23;
            H01.x = __float2bfloat16(v.x);  H01.y = __float2bfloat16(v.y);
            H23.x = __float2bfloat16(v.z);  H23.y = __float2bfloat16(v.w);
            L01.x = __float2bfloat16(v.x - __bfloat162float(H01.x));
            L01.y = __float2bfloat16(v.y - __bfloat162float(H01.y));
            L23.x = __float2bfloat16(v.z - __bfloat162float(H23.x));
            L23.y = __float2bfloat16(v.w - __bfloat162float(H23.y));
            uint2 hv, lv;
            hv.x = *reinterpret_cast<uint32_t*>(&H01);
            hv.y = *reinterpret_cast<uint32_t*>(&H23);
            lv.x = *reinterpret_cast<uint32_t*>(&L01);
            lv.y = *reinterpret_cast<uint32_t*>(&L23);
            *(uint2*)(Bh_out + idx2) = hv;
            *(uint2*)(Bl_out + idx2) = lv;
        }
    }
}

// ---------------------------------------------------------------------------
// Reduce v2 (tile-based, upper-only reads):
//   out[f] = c0[f]*I + sum_{k=1..KMAX} c_k[f] * T_k
// For tile (ti,tj): compute 4 filter sums on the upper block (direct coalesced
// writes) and, for ti != tj, mirror via smem transpose in 4 column strips.
// ---------------------------------------------------------------------------
__global__ void __launch_bounds__(256, 2)
reduce2_kernel(float* __restrict__ out)
{
    extern __shared__ float sm[];        // [4][32][RPITCH]
    const int tid = threadIdx.x;

    int ti = 0, rem = blockIdx.x;
    while (rem >= 32 - ti) { rem -= 32 - ti; ++ti; }
    const int tj = ti + rem;
    const int i0 = ti * BM;
    const int j0 = tj * BN;

    // coefficients in registers
    float cf[KMAX + 1][NF];
#pragma unroll
    for (int k = 0; k <= KMAX; ++k)
#pragma unroll
        for (int f = 0; f < NF; ++f) cf[k][f] = g_coef[k * NF + f];

    for (int s = 0; s < 4; ++s) {        // 4 strips of 32 cols
#pragma unroll
        for (int it = 0; it < 4; ++it) { // 1024 float4 per strip / 256 threads
            const int idx = it * 256 + tid;
            const int row = idx >> 3;            // 0..127
            const int c4 = idx & 7;              // float4 index within strip
            const int colg = j0 + s * 32 + c4 * 4;
            const size_t base = (size_t)(i0 + row) * NV + colg;

            float4 a0, a1, a2, a3;
            a0.x = a0.y = a0.z = a0.w = 0.0f; a1 = a0; a2 = a0; a3 = a0;
            // identity term on diagonal positions
            const int d = (i0 + row) - colg;     // matches col e when d == e
            if (d >= 0 && d < 4) {
                float* p0 = &a0.x; float* p1 = &a1.x;
                float* p2 = &a2.x; float* p3 = &a3.x;
                p0[d] += cf[0][0]; p1[d] += cf[0][1];
                p2[d] += cf[0][2]; p3[d] += cf[0][3];
            }
#pragma unroll
            for (int k = 1; k <= KMAX; ++k) {
                float4 t = *(const float4*)(g_T + (size_t)k * NNq + base);
                a0.x = fmaf(cf[k][0], t.x, a0.x); a0.y = fmaf(cf[k][0], t.y, a0.y);
                a0.z = fmaf(cf[k][0], t.z, a0.z); a0.w = fmaf(cf[k][0], t.w, a0.w);
                a1.x = fmaf(cf[k][1], t.x, a1.x); a1.y = fmaf(cf[k][1], t.y, a1.y);
                a1.z = fmaf(cf[k][1], t.z, a1.z); a1.w = fmaf(cf[k][1], t.w, a1.w);
                a2.x = fmaf(cf[k][2], t.x, a2.x); a2.y = fmaf(cf[k][2], t.y, a2.y);
                a2.z = fmaf(cf[k][2], t.z, a2.z); a2.w = fmaf(cf[k][2], t.w, a2.w);
                a3.x = fmaf(cf[k][3], t.x, a3.x); a3.y = fmaf(cf[k][3], t.y, a3.y);
                a3.z = fmaf(cf[k][3], t.z, a3.z); a3.w = fmaf(cf[k][3], t.w, a3.w);
            }
            *(float4*)(out + 0 * NNq + base) = a0;
            *(float4*)(out + 1 * NNq + base) = a1;
            *(float4*)(out + 2 * NNq + base) = a2;
            *(float4*)(out + 3 * NNq + base) = a3;

            if (ti != tj) {              // stash for transposed mirror
                const int cb = c4 * 4;   // col-in-strip base
                float* v[4] = {&a0.x, &a1.x, &a2.x, &a3.x};
#pragma unroll
                for (int f = 0; f < NF; ++f) {
                    float* base_f = sm + f * (32 * RPITCH);
#pragma unroll
                    for (int e = 0; e < 4; ++e)
                        base_f[(cb + e) * RPITCH + row] = v[f][e];
                }
            }
        }
        if (ti != tj) {
            __syncthreads();
#pragma unroll
            for (int f = 0; f < NF; ++f) {
                const float* base_f = sm + f * (32 * RPITCH);
                for (int u = tid; u < 32 * 32; u += 256) {
                    const int cl = u >> 5;           // strip col 0..31
                    const int r4 = (u & 31) * 4;     // original row, x4
                    float4 v = *(const float4*)&base_f[cl * RPITCH + r4];
                    *(float4*)(out + (size_t)f * NNq
                               + (size_t)(j0 + s * 32 + cl) * NV + i0 + r4) = v;
                }
            }
            __syncthreads();
        }
    }
}

// ---------------------------------------------------------------------------
extern "C" void kernel_launch(void* const* d_in, const int* in_sizes, int n_in,
                              void* d_out, int out_size)
{
    const float* L = (const float*)d_in[0];
    float* out = (float*)d_out;

    cudaFuncSetAttribute(cheb_mma_kernel,
                         cudaFuncAttributeMaxDynamicSharedMemorySize, SMEM_BYTES);
    cudaFuncSetAttribute(reduce2_kernel,
                         cudaFuncAttributeMaxDynamicSharedMemorySize, RSMEM);

    coef_kernel<<<1, 160>>>();
    prep_kernel<<<(int)(NNq / 256), 256>>>(L);

    for (int k = 2; k <= KMAX; ++k)
        cheb_mma_kernel<<<NTILES, 256, SMEM_BYTES>>>(k);

    reduce2_kernel<<<NTILES, 256, RSMEM>>>(out);
}

// round 17
// speedup vs baseline: 16.8731x; 5.9453x over previous
#include <cuda_runtime.h>
#include <cstdint>

#define NV 4096
#define NNq 16777216ULL          // NV*NV
#define NF 4
#define KMAX 7                   // truncation (calibrated: rel_err ~3.4e-4)
#define NCOEF 33
#define MAXNNZ 262144            // cap; actual nnz ~ 65K

// ---------------------------------------------------------------------------
// Static device scratch
// ---------------------------------------------------------------------------
__device__ float g_T[(KMAX + 1) * NNq];   // T_0..T_7, full fp32 matrices
__device__ int   g_rowcnt[NV];
__device__ int   g_rowptr[NV + 1];
__device__ int   g_cols[MAXNNZ];
__device__ float g_vals[MAXNNZ];          // 2 * L(i,j), off-diagonal only
__device__ float g_coef[NCOEF * NF];

// ---------------------------------------------------------------------------
// Chebyshev coefficients (fp64); sqrt(N)=64 and 0.5*c0 folded in
// ---------------------------------------------------------------------------
__global__ void coef_kernel() {
    int t = threadIdx.x;
    if (t >= NCOEF * NF) return;
    int o = t >> 2, f = t & 3;
    const double taus[4] = {0.5, 1.0, 2.0, 4.0};
    const double PI = 3.14159265358979323846;
    double s = 0.0;
    for (int j = 0; j < NCOEF; j++) {
        double u = (j + 0.5) / (double)NCOEF;
        double x = cos(PI * u) + 1.0;
        s += cos(PI * (double)o * u) * exp(-taus[f] * x);
    }
    double c = (2.0 / (double)NCOEF) * s * 64.0;
    if (o == 0) c *= 0.5;
    g_coef[o * NF + f] = (float)c;
}

// ---------------------------------------------------------------------------
// CSR build: count / scan / fill.  w_ij = 2*L(i,j) for j != i.
// (L(i,i) == 1 always -> Lhat = L - I has zero diagonal: excluded.)
// ---------------------------------------------------------------------------
__global__ void count_kernel(const float* __restrict__ L) {
    int w = (blockIdx.x * blockDim.x + threadIdx.x) >> 5;
    int lane = threadIdx.x & 31;
    if (w >= NV) return;
    const float* row = L + (size_t)w * NV;
    int cnt = 0;
    for (int b = 0; b < NV; b += 32) {
        float v = row[b + lane];
        unsigned m = __ballot_sync(0xffffffffu, v != 0.0f && (b + lane) != w);
        cnt += __popc(m);
    }
    if (lane == 0) g_rowcnt[w] = cnt;
}

__global__ void scan_kernel() {       // 1 block, 1024 threads
    __shared__ int sh[1024];
    int t = threadIdx.x;
    int4 c = *(const int4*)&g_rowcnt[t * 4];
    int s = c.x + c.y + c.z + c.w;
    sh[t] = s;
    __syncthreads();
    for (int off = 1; off < 1024; off <<= 1) {
        int v = (t >= off) ? sh[t - off] : 0;
        __syncthreads();
        sh[t] += v;
        __syncthreads();
    }
    int excl = (t == 0) ? 0 : sh[t - 1];
    g_rowptr[4 * t]     = excl;
    g_rowptr[4 * t + 1] = excl + c.x;
    g_rowptr[4 * t + 2] = excl + c.x + c.y;
    g_rowptr[4 * t + 3] = excl + c.x + c.y + c.z;
    if (t == 1023) g_rowptr[NV] = sh[1023];
}

__global__ void fill_kernel(const float* __restrict__ L) {
    int w = (blockIdx.x * blockDim.x + threadIdx.x) >> 5;
    int lane = threadIdx.x & 31;
    if (w >= NV) return;
    const float* row = L + (size_t)w * NV;
    int off = g_rowptr[w];
    for (int b = 0; b < NV; b += 32) {
        float v = row[b + lane];
        bool p = (v != 0.0f) && ((b + lane) != w);
        unsigned m = __ballot_sync(0xffffffffu, p);
        if (p) {
            int pos = off + __popc(m & ((1u << lane) - 1u));
            g_cols[pos] = b + lane;
            g_vals[pos] = 2.0f * v;
        }
        off += __popc(m);
    }
}

// ---------------------------------------------------------------------------
// Init: T0 = I, T1 = L - I (full fp32)
// ---------------------------------------------------------------------------
__global__ void init_kernel(const float* __restrict__ L) {
    size_t idx = (size_t)blockIdx.x * 256 + threadIdx.x;
    int i = (int)(idx >> 12), j = (int)(idx & (NV - 1));
    float l = L[idx];
    float d = (i == j) ? 1.0f : 0.0f;
    g_T[idx] = d;
    g_T[NNq + idx] = l - d;
}

// ---------------------------------------------------------------------------
// Sparse Chebyshev step: T_k(i,:) = sum_{j in N(i)} w_ij * T_{k-1}(j,:) - T_{k-2}(i,:)
// Warp handles one (row, 1024-col strip). Neighbor (col,val) pairs cached in
// lane registers (up to 64), broadcast via shfl; 2 col-chunks x 2 neighbors
// unrolled for memory-level parallelism. Exact fp32.
// ---------------------------------------------------------------------------
#define ROWS_PER_CTA 8
#define STRIP 1024

__device__ __forceinline__ void fma4(float4& acc, float s, const float4& t) {
    acc.x = fmaf(s, t.x, acc.x);
    acc.y = fmaf(s, t.y, acc.y);
    acc.z = fmaf(s, t.z, acc.z);
    acc.w = fmaf(s, t.w, acc.w);
}

__global__ void __launch_bounds__(256)
step_spmm(int k)
{
    const float* __restrict__ Tcur = g_T + (size_t)(k - 1) * NNq;
    const float* __restrict__ Told = g_T + (size_t)(k - 2) * NNq;
    float* __restrict__ Tnew = g_T + (size_t)k * NNq;

    const int wid = threadIdx.x >> 5;
    const int lane = threadIdx.x & 31;
    const int row = blockIdx.x * ROWS_PER_CTA + wid;
    const int s0 = blockIdx.y * STRIP;

    const int start = g_rowptr[row];
    const int n = g_rowptr[row + 1] - start;
    const int nn = (n < 64) ? n : 64;

    // cache up to 64 (col, val) pairs across lanes
    int c0v = 0, c1v = 0;
    float w0v = 0.0f, w1v = 0.0f;
    if (lane < n)      { c0v = g_cols[start + lane];      w0v = g_vals[start + lane]; }
    if (32 + lane < n) { c1v = g_cols[start + 32 + lane]; w1v = g_vals[start + 32 + lane]; }

    const size_t rowbase = (size_t)row * NV;

#pragma unroll
    for (int it = 0; it < 4; ++it) {
        const int cA = s0 + it * 256 + lane * 4;
        const int cB = cA + 128;
        float4 ta = *(const float4*)(Told + rowbase + cA);
        float4 tb = *(const float4*)(Told + rowbase + cB);
        float4 accA = make_float4(-ta.x, -ta.y, -ta.z, -ta.w);
        float4 accB = make_float4(-tb.x, -tb.y, -tb.z, -tb.w);

        int e = 0;
        for (; e + 2 <= nn; e += 2) {
            const int e1 = e + 1;
            const int   j0 = __shfl_sync(0xffffffffu, (e  < 32) ? c0v : c1v, e  & 31);
            const float q0 = __shfl_sync(0xffffffffu, (e  < 32) ? w0v : w1v, e  & 31);
            const int   j1 = __shfl_sync(0xffffffffu, (e1 < 32) ? c0v : c1v, e1 & 31);
            const float q1 = __shfl_sync(0xffffffffu, (e1 < 32) ? w0v : w1v, e1 & 31);
            float4 a0 = *(const float4*)(Tcur + (size_t)j0 * NV + cA);
            float4 b0 = *(const float4*)(Tcur + (size_t)j0 * NV + cB);
            float4 a1 = *(const float4*)(Tcur + (size_t)j1 * NV + cA);
            float4 b1 = *(const float4*)(Tcur + (size_t)j1 * NV + cB);
            fma4(accA, q0, a0); fma4(accB, q0, b0);
            fma4(accA, q1, a1); fma4(accB, q1, b1);
        }
        if (e < nn) {
            const int   j0 = __shfl_sync(0xffffffffu, (e < 32) ? c0v : c1v, e & 31);
            const float q0 = __shfl_sync(0xffffffffu, (e < 32) ? w0v : w1v, e & 31);
            float4 a0 = *(const float4*)(Tcur + (size_t)j0 * NV + cA);
            float4 b0 = *(const float4*)(Tcur + (size_t)j0 * NV + cB);
            fma4(accA, q0, a0); fma4(accB, q0, b0);
        }
        // rare overflow path (row degree > 64): read CSR directly
        for (int e2 = 64; e2 < n; ++e2) {
            const int   j0 = g_cols[start + e2];
            const float q0 = g_vals[start + e2];
            float4 a0 = *(const float4*)(Tcur + (size_t)j0 * NV + cA);
            float4 b0 = *(const float4*)(Tcur + (size_t)j0 * NV + cB);
            fma4(accA, q0, a0); fma4(accB, q0, b0);
        }

        *(float4*)(Tnew + rowbase + cA) = accA;
        *(float4*)(Tnew + rowbase + cB) = accB;
    }
}

// ---------------------------------------------------------------------------
// Final reduction: out[f] = c0[f]*I + sum_{k=1..KMAX} c_k[f] * T_k
// ---------------------------------------------------------------------------
__global__ void reduce_kernel(float* __restrict__ out) {
    size_t e = (size_t)blockIdx.x * 256 + threadIdx.x;
    size_t base = e * 4;
    int i = (int)(base >> 12);
    int jb = (int)(base & (NV - 1));
    float4 acc[NF];
#pragma unroll
    for (int f = 0; f < NF; ++f) {
        float c0 = g_coef[f];
        acc[f].x = (i == jb + 0) ? c0 : 0.0f;
        acc[f].y = (i == jb + 1) ? c0 : 0.0f;
        acc[f].z = (i == jb + 2) ? c0 : 0.0f;
        acc[f].w = (i == jb + 3) ? c0 : 0.0f;
    }
    for (int k = 1; k <= KMAX; ++k) {
        float4 t = *(const float4*)(g_T + (size_t)k * NNq + base);
#pragma unroll
        for (int f = 0; f < NF; ++f) {
            float c = g_coef[k * NF + f];
            acc[f].x = fmaf(c, t.x, acc[f].x);
            acc[f].y = fmaf(c, t.y, acc[f].y);
            acc[f].z = fmaf(c, t.z, acc[f].z);
            acc[f].w = fmaf(c, t.w, acc[f].w);
        }
    }
#pragma unroll
    for (int f = 0; f < NF; ++f)
        *(float4*)(out + (size_t)f * NNq + base) = acc[f];
}

// ---------------------------------------------------------------------------
extern "C" void kernel_launch(void* const* d_in, const int* in_sizes, int n_in,
                              void* d_out, int out_size)
{
    const float* L = (const float*)d_in[0];
    float* out = (float*)d_out;

    coef_kernel<<<1, 160>>>();
    count_kernel<<<NV / 8, 256>>>(L);     // 512 blocks x 8 warps = 4096 rows
    scan_kernel<<<1, 1024>>>();
    fill_kernel<<<NV / 8, 256>>>(L);
    init_kernel<<<(int)(NNq / 256), 256>>>(L);

    dim3 grid(NV / ROWS_PER_CTA, NV / STRIP);   // (512, 4)
    for (int k = 2; k <= KMAX; ++k)
        step_spmm<<<grid, 256>>>(k);

    reduce_kernel<<<(int)(NNq / 4 / 256), 256>>>(out);
}